// round 12
// baseline (speedup 1.0000x reference)
#include <cuda_runtime.h>
#include <math.h>

#define BB 8
#define NN 512
#define DMODEL 1024
#define HH 16
#define DK 64

// ---- static scratch ----
__device__ float g_q[BB*HH*NN*DK];        // tf32-pre-rounded after projection
__device__ float g_k[BB*HH*NN*DK];
__device__ float g_v[BB*HH*NN*DK];
__device__ float g_s[BB*HH*NN*NN];        // geometry bias (log g), fp32
__device__ float g_o1[BB*NN*DMODEL];      // attn output, tf32-pre-rounded
__device__ float g_boxf[BB*NN*6];
__device__ float g_act[3*BB*NN*DMODEL];   // tf32-rounded activations
__device__ float g_wr[4*DMODEL*DMODEL];   // tf32-rounded weights Wq,Wk,Wv,Wo

// ---- helpers ----
__device__ __forceinline__ unsigned f2tf(float f) {
    unsigned u; asm("cvt.rna.tf32.f32 %0, %1;" : "=r"(u) : "f"(f)); return u;
}
__device__ __forceinline__ float r2(float f) { return __uint_as_float(f2tf(f)); }
__device__ __forceinline__ void mma8(float* c, const unsigned* a, const unsigned* b) {
    asm volatile("mma.sync.aligned.m16n8k8.row.col.f32.tf32.tf32.f32 "
        "{%0,%1,%2,%3},{%4,%5,%6,%7},{%8,%9},{%0,%1,%2,%3};"
        : "+f"(c[0]), "+f"(c[1]), "+f"(c[2]), "+f"(c[3])
        : "r"(a[0]), "r"(a[1]), "r"(a[2]), "r"(a[3]), "r"(b[0]), "r"(b[1]));
}
__device__ __forceinline__ void ldsm4(unsigned& r0, unsigned& r1, unsigned& r2v,
                                      unsigned& r3, unsigned a) {
    asm volatile("ldmatrix.sync.aligned.m8n8.x4.shared.b16 {%0,%1,%2,%3}, [%4];"
        : "=r"(r0), "=r"(r1), "=r"(r2v), "=r"(r3) : "r"(a));
}
__device__ __forceinline__ void cpa16(unsigned dst, const void* src) {
    asm volatile("cp.async.cg.shared.global [%0], [%1], 16;" :: "r"(dst), "l"(src));
}
__device__ __forceinline__ void cp_commit() {
    asm volatile("cp.async.commit_group;" ::: "memory");
}
__device__ __forceinline__ void cp_wait1() {
    asm volatile("cp.async.wait_group 1;" ::: "memory");
}
__device__ __forceinline__ void cp_wait0() {
    asm volatile("cp.async.wait_group 0;" ::: "memory");
}
__device__ __forceinline__ unsigned smaddr(const void* p) {
    return (unsigned)__cvta_generic_to_shared(p);
}
__device__ __forceinline__ unsigned long long pack2(float x, float y) {
    unsigned long long r; asm("mov.b64 %0,{%1,%2};" : "=l"(r) : "f"(x), "f"(y)); return r;
}
__device__ __forceinline__ void unpack2(unsigned long long v, float& x, float& y) {
    asm("mov.b64 {%0,%1},%2;" : "=f"(x), "=f"(y) : "l"(v));
}
__device__ __forceinline__ unsigned long long fma2(unsigned long long a, unsigned long long b,
                                                   unsigned long long c) {
    unsigned long long d;
    asm("fma.rn.f32x2 %0,%1,%2,%3;" : "=l"(d) : "l"(a), "l"(b), "l"(c)); return d;
}

// ============================================================
// box features
// ============================================================
__global__ void boxfeat_kernel(const float* __restrict__ boxes) {
    int i = blockIdx.x * blockDim.x + threadIdx.x;
    if (i >= BB*NN) return;
    float4 bx = ((const float4*)boxes)[i];
    float cx = 0.5f * (bx.x + bx.z);
    float cy = 0.5f * (bx.y + bx.w);
    float w  = bx.z - bx.x + 1.0f;
    float h  = bx.w - bx.y + 1.0f;
    float* o = &g_boxf[i*6];
    o[0] = cx; o[1] = cy;
    o[2] = 1.0f / w; o[3] = 1.0f / h;
    o[4] = __logf(w); o[5] = __logf(h);
}

// ============================================================
// pre-round activations + weights to tf32 (rna)
// ============================================================
__global__ void prep_kernel(const float* __restrict__ q, const float* __restrict__ k,
                            const float* __restrict__ v, const float* __restrict__ wq,
                            const float* __restrict__ wk, const float* __restrict__ wv,
                            const float* __restrict__ wo) {
    int z = blockIdx.y;
    const float* src = (z==0)?q:(z==1)?k:(z==2)?v:(z==3)?wq:(z==4)?wk:(z==5)?wv:wo;
    float* dst = (z < 3) ? g_act + (size_t)z*(BB*NN*DMODEL)
                         : g_wr + (size_t)(z-3)*(DMODEL*DMODEL);
    int n4 = (z < 3) ? (BB*NN*DMODEL/4) : (DMODEL*DMODEL/4);
    int i = blockIdx.x*256 + threadIdx.x;
    if (i < n4) {
        float4 a = ((const float4*)src)[i];
        ((uint4*)dst)[i] = make_uint4(f2tf(a.x), f2tf(a.y), f2tf(a.z), f2tf(a.w));
    }
}

// ============================================================
// geometry bias, packed f32x2 over head pairs
// ============================================================
__global__ void __launch_bounds__(256) geom_kernel(const float* __restrict__ Wg,
                                                   const float* __restrict__ bg) {
    __shared__ unsigned long long WgS2[32][8];
    __shared__ unsigned long long WgC2[32][8];
    __shared__ float qf[16][6];
    __shared__ float kf[16][6];
    __shared__ float bgs[16];
    int tid = threadIdx.x;
    int b  = blockIdx.z;
    int q0 = blockIdx.y * 16, k0 = blockIdx.x * 16;

    {
        int i = tid >> 3, p = tid & 7;
        WgS2[i][p] = pack2(Wg[(2*p)*64 + i],      Wg[(2*p+1)*64 + i]);
        WgC2[i][p] = pack2(Wg[(2*p)*64 + 32 + i], Wg[(2*p+1)*64 + 32 + i]);
    }
    if (tid < 16) {
        bgs[tid] = bg[tid];
        #pragma unroll
        for (int j = 0; j < 6; j++) qf[tid][j] = g_boxf[(b*NN + q0 + tid)*6 + j];
    } else if (tid < 32) {
        int t = tid - 16;
        #pragma unroll
        for (int j = 0; j < 6; j++) kf[t][j] = g_boxf[(b*NN + k0 + t)*6 + j];
    }
    __syncthreads();

    int ty = tid >> 4, tx = tid & 15;
    float pos[4];
    pos[0] = __logf(fmaxf(fabsf(qf[ty][0] - kf[tx][0]) * qf[ty][2], 1e-3f));
    pos[1] = __logf(fmaxf(fabsf(qf[ty][1] - kf[tx][1]) * qf[ty][3], 1e-3f));
    pos[2] = qf[ty][4] - kf[tx][4];
    pos[3] = qf[ty][5] - kf[tx][5];

    unsigned long long acc2[8];
    #pragma unroll
    for (int p = 0; p < 8; p++) acc2[p] = pack2(bgs[2*p], bgs[2*p+1]);

    const float dm[8] = {1.0f, 0.42169650f, 0.17782794f, 0.07498942f,
                         0.03162278f, 0.01333521f, 0.00562341f, 0.00237137f};
    #pragma unroll
    for (int c = 0; c < 4; c++) {
        float p100 = 100.0f * pos[c];
        #pragma unroll
        for (int f = 0; f < 8; f++) {
            float s, co;
            __sincosf(p100 * dm[f], &s, &co);
            unsigned long long s2 = pack2(s, s), c2 = pack2(co, co);
            int idx = c*8 + f;
            #pragma unroll
            for (int p = 0; p < 8; p++) {
                unsigned long long t = fma2(c2, WgC2[idx][p], acc2[p]);
                acc2[p] = fma2(s2, WgS2[idx][p], t);
            }
        }
    }
    int q = q0 + ty, k = k0 + tx;
    #pragma unroll
    for (int p = 0; p < 8; p++) {
        float x, y;
        unpack2(acc2[p], x, y);
        g_s[(((size_t)b*HH + 2*p  )*NN + q)*NN + k] = __logf(fmaxf(x, 1e-6f));
        g_s[(((size_t)b*HH + 2*p+1)*NN + q)*NN + k] = __logf(fmaxf(y, 1e-6f));
    }
}

// ============================================================
// tf32 GEMM, 128x128 CTA tile, 4 warps of 64x64, KTILE=32, 3-stage cp.async,
// LDSM fragments, no in-loop CVT (inputs pre-rounded).
// MODE 0: QKV (A=g_act[z], B=g_wr[z], rounded scatter to g_q/g_k/g_v)
// MODE 1: O-proj (A=g_o1, B=g_wr[3], dst=Cout, unrounded)
// ============================================================
#define GST 36                              // smem row stride (words) for K=32 + pad
#define GTILEW (128*GST)                    // words per matrix per stage
#define GSMEM (3 * 2 * GTILEW * 4)          // 110592 B

template<int MODE>
__global__ void __launch_bounds__(128, 2) gemm_tc(
    const float* __restrict__ b0p, const float* __restrict__ b1p,
    const float* __restrict__ b2p, float* __restrict__ Cout)
{
    constexpr int KD  = DMODEL;
    constexpr int NIT = KD / 32;            // 32 chunks
    extern __shared__ float gsm[];

    int t = threadIdx.x;
    int m0 = blockIdx.y * 128, n0 = blockIdx.x * 128;
    int z = blockIdx.z;

    const float *A, *B, *bias;
    if (MODE == 0) {
        A = g_act + (size_t)z*(BB*NN*DMODEL);
        B = g_wr  + (size_t)z*(DMODEL*DMODEL);
        bias = (z == 0) ? b0p : (z == 1) ? b1p : b2p;
    } else {
        A = g_o1;
        B = g_wr + 3*(size_t)(DMODEL*DMODEL);
        bias = b0p;
    }

    // per-thread load slots: 8 chunks of A + 8 of B per stage (128 threads)
    int lrows[8], lc8[8];
    #pragma unroll
    for (int i = 0; i < 8; i++) {
        int idx = t + i*128;
        lrows[i] = idx >> 3;
        lc8[i]   = (idx & 7) * 4;
    }
    unsigned sbase = smaddr(gsm);

    int w = t >> 5, l = t & 31;
    int wm = w & 1, wn = w >> 1;            // 2x2 warps of 64x64
    int lj   = l & 7;
    int aRow = ((l >> 3) & 1) * 8 + lj;
    int aCol = (l >> 4) * 4;
    int bRow = (l >> 4) * 8 + lj;
    int bCol = ((l >> 3) & 1) * 4;

    float acc[4][8][4];
    #pragma unroll
    for (int i = 0; i < 4; i++)
        #pragma unroll
        for (int j = 0; j < 8; j++)
            #pragma unroll
            for (int k = 0; k < 4; k++) acc[i][j][k] = 0.0f;

    // prologue: chunks 0,1 -> stages 0,1
    #pragma unroll
    for (int p = 0; p < 2; p++) {
        unsigned ab = sbase + (unsigned)(p*2*GTILEW)*4u;
        #pragma unroll
        for (int i = 0; i < 8; i++) {
            cpa16(ab + (lrows[i]*GST + lc8[i])*4u,
                  A + (size_t)(m0 + lrows[i])*KD + p*32 + lc8[i]);
            cpa16(ab + (GTILEW + lrows[i]*GST + lc8[i])*4u,
                  B + (size_t)(n0 + lrows[i])*KD + p*32 + lc8[i]);
        }
        cp_commit();
    }

    for (int j = 0; j < NIT; j++) {
        cp_wait1();
        __syncthreads();
        if (j + 2 < NIT) {
            int s = (j + 2) % 3;
            unsigned ab = sbase + (unsigned)(s*2*GTILEW)*4u;
            int kb = (j + 2) * 32;
            #pragma unroll
            for (int i = 0; i < 8; i++) {
                cpa16(ab + (lrows[i]*GST + lc8[i])*4u,
                      A + (size_t)(m0 + lrows[i])*KD + kb + lc8[i]);
                cpa16(ab + (GTILEW + lrows[i]*GST + lc8[i])*4u,
                      B + (size_t)(n0 + lrows[i])*KD + kb + lc8[i]);
            }
        }
        cp_commit();

        int s = j % 3;
        const float* As = gsm + s*2*GTILEW;
        const float* Bs = As + GTILEW;
        #pragma unroll
        for (int kc = 0; kc < 4; kc++) {
            unsigned a[4][4];
            #pragma unroll
            for (int mf = 0; mf < 4; mf++)
                ldsm4(a[mf][0], a[mf][1], a[mf][2], a[mf][3],
                      smaddr(&As[(wm*64 + mf*16 + aRow)*GST + kc*8 + aCol]));
            #pragma unroll
            for (int p = 0; p < 4; p++) {
                unsigned bb[4];
                ldsm4(bb[0], bb[1], bb[2], bb[3],
                      smaddr(&Bs[(wn*64 + p*16 + bRow)*GST + kc*8 + bCol]));
                #pragma unroll
                for (int mf = 0; mf < 4; mf++) {
                    mma8(acc[mf][2*p],   a[mf], bb);
                    mma8(acc[mf][2*p+1], a[mf], bb + 2);
                }
            }
        }
    }

    // epilogue
    #pragma unroll
    for (int mf = 0; mf < 4; mf++) {
        #pragma unroll
        for (int nf = 0; nf < 8; nf++) {
            int col = n0 + wn*64 + nf*8 + 2*(l & 3);
            float2 b2 = *(const float2*)(bias + col);
            #pragma unroll
            for (int rr = 0; rr < 2; rr++) {
                int row = m0 + wm*64 + mf*16 + rr*8 + (l >> 2);
                float v0 = acc[mf][nf][rr*2 + 0] + b2.x;
                float v1 = acc[mf][nf][rr*2 + 1] + b2.y;
                if (MODE == 0) {
                    int h = col >> 6, d = col & 63;
                    int bq = row >> 9, ntok = row & (NN-1);
                    float* dstp = (z == 0) ? g_q : (z == 1) ? g_k : g_v;
                    *(float2*)&dstp[(((size_t)bq*HH + h)*NN + ntok)*DK + d] =
                        make_float2(r2(v0), r2(v1));
                } else {
                    *(float2*)&Cout[(size_t)row*DMODEL + col] = make_float2(v0, v1);
                }
            }
        }
    }
}

// ============================================================
// fused attention: S = bias + (Q/8)Kt, online softmax, O += P V
// (unchanged)
// ============================================================
#define KS_ST 68
#define VS_ST 72
#define PS_ST 68
#define FUSED_SMEM ((2*64*KS_ST + 2*64*VS_ST + 128*PS_ST) * 4)

__global__ void __launch_bounds__(256, 2) fused_attn() {
    extern __shared__ float smf[];
    float* KsB = smf;
    float* VsB = smf + 2*64*KS_ST;
    float* Ps  = VsB + 2*64*VS_ST;

    int t = threadIdx.x;
    int bh = blockIdx.y;
    int q0 = blockIdx.x * 128;
    const float* Qg = g_q + ((size_t)bh*NN + q0)*DK;
    const float* Kg = g_k + (size_t)bh*NN*DK;
    const float* Vg = g_v + (size_t)bh*NN*DK;
    const float* Sg = g_s + (size_t)bh*NN*NN;

    int w = t >> 5, l = t & 31;
    int r0 = l >> 2, c0 = l & 3;
    int qrow = w*16 + r0;
    int lj   = l & 7;
    int aRow = ((l >> 3) & 1) * 8 + lj;
    int aCol = (l >> 4) * 4;
    int bRow = (l >> 4) * 8 + lj;
    int bCol = ((l >> 3) & 1) * 4;

    #pragma unroll
    for (int i = 0; i < 8; i++) {
        int idx = t + i*256;
        int row = idx >> 4, col = (idx & 15) * 4;
        cpa16(smaddr(Ps + row*PS_ST + col), Qg + row*DK + col);
    }
    #pragma unroll
    for (int i = 0; i < 4; i++) {
        int idx = t + i*256;
        int row = idx >> 4, col = (idx & 15) * 4;
        cpa16(smaddr(KsB + row*KS_ST + col), Kg + row*DK + col);
        cpa16(smaddr(VsB + row*VS_ST + col), Vg + row*DK + col);
    }
    cp_commit();
    cp_wait0();
    __syncthreads();

    unsigned qa[8][4];
    #pragma unroll
    for (int kc = 0; kc < 8; kc++) {
        qa[kc][0] = __float_as_uint(0.125f * Ps[qrow*PS_ST     + kc*8 + c0]);
        qa[kc][1] = __float_as_uint(0.125f * Ps[(qrow+8)*PS_ST + kc*8 + c0]);
        qa[kc][2] = __float_as_uint(0.125f * Ps[qrow*PS_ST     + kc*8 + c0 + 4]);
        qa[kc][3] = __float_as_uint(0.125f * Ps[(qrow+8)*PS_ST + kc*8 + c0 + 4]);
    }

    float Oa[8][4];
    #pragma unroll
    for (int nf = 0; nf < 8; nf++)
        #pragma unroll
        for (int k = 0; k < 4; k++) Oa[nf][k] = 0.0f;
    float m0v = -INFINITY, m1v = -INFINITY, l0v = 0.0f, l1v = 0.0f;

    const int NT = NN / 64;
    for (int j = 0; j < NT; j++) {
        if (j > 0) cp_wait0();
        __syncthreads();
        if (j + 1 < NT) {
            int nb = (j + 1) & 1;
            float* Ksn = KsB + nb*64*KS_ST;
            float* Vsn = VsB + nb*64*VS_ST;
            #pragma unroll
            for (int i = 0; i < 4; i++) {
                int idx = t + i*256;
                int row = idx >> 4, col = (idx & 15) * 4;
                cpa16(smaddr(Ksn + row*KS_ST + col), Kg + ((j+1)*64 + row)*DK + col);
                cpa16(smaddr(Vsn + row*VS_ST + col), Vg + ((j+1)*64 + row)*DK + col);
            }
        }
        cp_commit();

        const float* Ks = KsB + (j & 1)*64*KS_ST;
        const float* Vs = VsB + (j & 1)*64*VS_ST;

        float acc[8][4];
        {
            const float* br0 = Sg + (size_t)(q0 + qrow)*NN + j*64;
            const float* br1 = br0 + 8*NN;
            #pragma unroll
            for (int nf = 0; nf < 8; nf++) {
                float2 t0 = *(const float2*)(br0 + nf*8 + 2*c0);
                float2 t1 = *(const float2*)(br1 + nf*8 + 2*c0);
                acc[nf][0] = t0.x; acc[nf][1] = t0.y;
                acc[nf][2] = t1.x; acc[nf][3] = t1.y;
            }
        }
        #pragma unroll
        for (int kc = 0; kc < 8; kc++) {
            #pragma unroll
            for (int p = 0; p < 4; p++) {
                unsigned bb[4];
                ldsm4(bb[0], bb[1], bb[2], bb[3],
                      smaddr(&Ks[(p*16 + bRow)*KS_ST + kc*8 + bCol]));
                mma8(acc[2*p],   qa[kc], bb);
                mma8(acc[2*p+1], qa[kc], bb + 2);
            }
        }

        float mx0 = -INFINITY, mx1 = -INFINITY;
        #pragma unroll
        for (int nf = 0; nf < 8; nf++) {
            mx0 = fmaxf(mx0, fmaxf(acc[nf][0], acc[nf][1]));
            mx1 = fmaxf(mx1, fmaxf(acc[nf][2], acc[nf][3]));
        }
        #pragma unroll
        for (int o = 1; o <= 2; o <<= 1) {
            mx0 = fmaxf(mx0, __shfl_xor_sync(0xffffffffu, mx0, o));
            mx1 = fmaxf(mx1, __shfl_xor_sync(0xffffffffu, mx1, o));
        }
        float mn0 = fmaxf(m0v, mx0), mn1 = fmaxf(m1v, mx1);
        float sc0 = __expf(m0v - mn0), sc1 = __expf(m1v - mn1);
        m0v = mn0; m1v = mn1;
        float s0 = 0.0f, s1 = 0.0f;
        #pragma unroll
        for (int nf = 0; nf < 8; nf++) {
            acc[nf][0] = __expf(acc[nf][0] - mn0);
            acc[nf][1] = __expf(acc[nf][1] - mn0);
            acc[nf][2] = __expf(acc[nf][2] - mn1);
            acc[nf][3] = __expf(acc[nf][3] - mn1);
            s0 += acc[nf][0] + acc[nf][1];
            s1 += acc[nf][2] + acc[nf][3];
        }
        #pragma unroll
        for (int o = 1; o <= 2; o <<= 1) {
            s0 += __shfl_xor_sync(0xffffffffu, s0, o);
            s1 += __shfl_xor_sync(0xffffffffu, s1, o);
        }
        l0v = l0v * sc0 + s0;
        l1v = l1v * sc1 + s1;
        #pragma unroll
        for (int nf = 0; nf < 8; nf++) {
            Oa[nf][0] *= sc0; Oa[nf][1] *= sc0;
            Oa[nf][2] *= sc1; Oa[nf][3] *= sc1;
        }

        #pragma unroll
        for (int nf = 0; nf < 8; nf++) {
            *(float2*)&Ps[qrow*PS_ST     + nf*8 + 2*c0] =
                make_float2(r2(acc[nf][0]), r2(acc[nf][1]));
            *(float2*)&Ps[(qrow+8)*PS_ST + nf*8 + 2*c0] =
                make_float2(r2(acc[nf][2]), r2(acc[nf][3]));
        }
        __syncwarp();
        #pragma unroll
        for (int kc = 0; kc < 8; kc++) {
            unsigned a4[4];
            ldsm4(a4[0], a4[1], a4[2], a4[3],
                  smaddr(&Ps[(w*16 + aRow)*PS_ST + kc*8 + aCol]));
            #pragma unroll
            for (int nf = 0; nf < 8; nf++) {
                unsigned b[2];
                b[0] = __float_as_uint(Vs[(kc*8 + c0    )*VS_ST + r0 + nf*8]);
                b[1] = __float_as_uint(Vs[(kc*8 + c0 + 4)*VS_ST + r0 + nf*8]);
                mma8(Oa[nf], a4, b);
            }
        }
        __syncwarp();
    }

    float inv0 = 1.0f / l0v, inv1 = 1.0f / l1v;
    int b = bh >> 4, h = bh & 15;
    float* O0 = g_o1 + ((size_t)b*NN + q0 + qrow)*DMODEL + h*DK;
    float* O1 = O0 + 8*DMODEL;
    #pragma unroll
    for (int nf = 0; nf < 8; nf++) {
        *(float2*)(O0 + nf*8 + 2*c0) =
            make_float2(r2(Oa[nf][0]*inv0), r2(Oa[nf][1]*inv0));
        *(float2*)(O1 + nf*8 + 2*c0) =
            make_float2(r2(Oa[nf][2]*inv1), r2(Oa[nf][3]*inv1));
    }
}

// ============================================================
extern "C" void kernel_launch(void* const* d_in, const int* in_sizes, int n_in,
                              void* d_out, int out_size) {
    const float* queries = (const float*)d_in[0];
    const float* keys    = (const float*)d_in[1];
    const float* values  = (const float*)d_in[2];
    const float* boxes   = (const float*)d_in[3];
    const float* Wq = (const float*)d_in[4];
    const float* bq = (const float*)d_in[5];
    const float* Wk = (const float*)d_in[6];
    const float* bk = (const float*)d_in[7];
    const float* Wv = (const float*)d_in[8];
    const float* bv = (const float*)d_in[9];
    const float* Wo = (const float*)d_in[10];
    const float* bo = (const float*)d_in[11];
    const float* Wg = (const float*)d_in[12];
    const float* bg = (const float*)d_in[13];
    float* out = (float*)d_out;

    cudaFuncSetAttribute(gemm_tc<0>, cudaFuncAttributeMaxDynamicSharedMemorySize, GSMEM);
    cudaFuncSetAttribute(gemm_tc<1>, cudaFuncAttributeMaxDynamicSharedMemorySize, GSMEM);
    cudaFuncSetAttribute(fused_attn, cudaFuncAttributeMaxDynamicSharedMemorySize,
                         FUSED_SMEM);

    boxfeat_kernel<<<16, 256>>>(boxes);
    prep_kernel<<<dim3(4096, 7), 256>>>(queries, keys, values, Wq, Wk, Wv, Wo);
    geom_kernel<<<dim3(32, 32, 8), 256>>>(Wg, bg);
    gemm_tc<0><<<dim3(8, 32, 3), 128, GSMEM>>>(bq, bk, bv, nullptr);
    fused_attn<<<dim3(4, 128), 256, FUSED_SMEM>>>();
    gemm_tc<1><<<dim3(8, 32, 1), 128, GSMEM>>>(bo, nullptr, nullptr, out);
}

// round 13
// speedup vs baseline: 1.2491x; 1.2491x over previous
#include <cuda_runtime.h>
#include <cuda_fp16.h>
#include <math.h>

#define BB 8
#define NN 512
#define DMODEL 1024
#define HH 16
#define DK 64

// ---- static scratch ----
__device__ float g_q[BB*HH*NN*DK];        // tf32-pre-rounded after projection
__device__ float g_k[BB*HH*NN*DK];
__device__ float g_v[BB*HH*NN*DK];
__device__ float g_s[BB*HH*NN*NN];        // geometry bias (log g), fp32
__device__ __half g_o1h[BB*NN*DMODEL];    // attn output, fp16 (feeds O-proj)
__device__ float g_boxf[BB*NN*6];
__device__ __half g_acth[3*BB*NN*DMODEL]; // fp16 activations (q,k,v inputs)
__device__ __half g_wh[4*DMODEL*DMODEL];  // fp16 weights Wq,Wk,Wv,Wo

// ---- helpers ----
__device__ __forceinline__ unsigned f2tf(float f) {
    unsigned u; asm("cvt.rna.tf32.f32 %0, %1;" : "=r"(u) : "f"(f)); return u;
}
__device__ __forceinline__ float r2(float f) { return __uint_as_float(f2tf(f)); }
__device__ __forceinline__ void mma8(float* c, const unsigned* a, const unsigned* b) {
    asm volatile("mma.sync.aligned.m16n8k8.row.col.f32.tf32.tf32.f32 "
        "{%0,%1,%2,%3},{%4,%5,%6,%7},{%8,%9},{%0,%1,%2,%3};"
        : "+f"(c[0]), "+f"(c[1]), "+f"(c[2]), "+f"(c[3])
        : "r"(a[0]), "r"(a[1]), "r"(a[2]), "r"(a[3]), "r"(b[0]), "r"(b[1]));
}
__device__ __forceinline__ void mma16h(float* c, const unsigned* a,
                                       unsigned b0, unsigned b1) {
    asm volatile("mma.sync.aligned.m16n8k16.row.col.f32.f16.f16.f32 "
        "{%0,%1,%2,%3},{%4,%5,%6,%7},{%8,%9},{%0,%1,%2,%3};"
        : "+f"(c[0]), "+f"(c[1]), "+f"(c[2]), "+f"(c[3])
        : "r"(a[0]), "r"(a[1]), "r"(a[2]), "r"(a[3]), "r"(b0), "r"(b1));
}
__device__ __forceinline__ void ldsm4(unsigned& r0, unsigned& r1, unsigned& r2v,
                                      unsigned& r3, unsigned a) {
    asm volatile("ldmatrix.sync.aligned.m8n8.x4.shared.b16 {%0,%1,%2,%3}, [%4];"
        : "=r"(r0), "=r"(r1), "=r"(r2v), "=r"(r3) : "r"(a));
}
__device__ __forceinline__ void cpa16(unsigned dst, const void* src) {
    asm volatile("cp.async.cg.shared.global [%0], [%1], 16;" :: "r"(dst), "l"(src));
}
__device__ __forceinline__ void cp_commit() {
    asm volatile("cp.async.commit_group;" ::: "memory");
}
__device__ __forceinline__ void cp_wait1() {
    asm volatile("cp.async.wait_group 1;" ::: "memory");
}
__device__ __forceinline__ void cp_wait0() {
    asm volatile("cp.async.wait_group 0;" ::: "memory");
}
__device__ __forceinline__ unsigned smaddr(const void* p) {
    return (unsigned)__cvta_generic_to_shared(p);
}
__device__ __forceinline__ unsigned long long pack2(float x, float y) {
    unsigned long long r; asm("mov.b64 %0,{%1,%2};" : "=l"(r) : "f"(x), "f"(y)); return r;
}
__device__ __forceinline__ void unpack2(unsigned long long v, float& x, float& y) {
    asm("mov.b64 {%0,%1},%2;" : "=f"(x), "=f"(y) : "l"(v));
}
__device__ __forceinline__ unsigned long long fma2(unsigned long long a, unsigned long long b,
                                                   unsigned long long c) {
    unsigned long long d;
    asm("fma.rn.f32x2 %0,%1,%2,%3;" : "=l"(d) : "l"(a), "l"(b), "l"(c)); return d;
}

// ============================================================
// box features
// ============================================================
__global__ void boxfeat_kernel(const float* __restrict__ boxes) {
    int i = blockIdx.x * blockDim.x + threadIdx.x;
    if (i >= BB*NN) return;
    float4 bx = ((const float4*)boxes)[i];
    float cx = 0.5f * (bx.x + bx.z);
    float cy = 0.5f * (bx.y + bx.w);
    float w  = bx.z - bx.x + 1.0f;
    float h  = bx.w - bx.y + 1.0f;
    float* o = &g_boxf[i*6];
    o[0] = cx; o[1] = cy;
    o[2] = 1.0f / w; o[3] = 1.0f / h;
    o[4] = __logf(w); o[5] = __logf(h);
}

// ============================================================
// convert activations + weights to fp16
// z: 0-2 = queries/keys/values -> g_acth; 3-6 = Wq/Wk/Wv/Wo -> g_wh
// ============================================================
__global__ void prep_kernel(const float* __restrict__ q, const float* __restrict__ k,
                            const float* __restrict__ v, const float* __restrict__ wq,
                            const float* __restrict__ wk, const float* __restrict__ wv,
                            const float* __restrict__ wo) {
    int z = blockIdx.y;
    const float* src = (z==0)?q:(z==1)?k:(z==2)?v:(z==3)?wq:(z==4)?wk:(z==5)?wv:wo;
    __half* dst = (z < 3) ? g_acth + (size_t)z*(BB*NN*DMODEL)
                          : g_wh + (size_t)(z-3)*(DMODEL*DMODEL);
    int n4 = (z < 3) ? (BB*NN*DMODEL/4) : (DMODEL*DMODEL/4);
    int i = blockIdx.x*256 + threadIdx.x;
    if (i < n4) {
        float4 a = ((const float4*)src)[i];
        __half2 h0 = __floats2half2_rn(a.x, a.y);
        __half2 h1 = __floats2half2_rn(a.z, a.w);
        ((__half2*)dst)[2*i]   = h0;
        ((__half2*)dst)[2*i+1] = h1;
    }
}

// ============================================================
// geometry bias, packed f32x2 over head pairs
// ============================================================
__global__ void __launch_bounds__(256) geom_kernel(const float* __restrict__ Wg,
                                                   const float* __restrict__ bg) {
    __shared__ unsigned long long WgS2[32][8];
    __shared__ unsigned long long WgC2[32][8];
    __shared__ float qf[16][6];
    __shared__ float kf[16][6];
    __shared__ float bgs[16];
    int tid = threadIdx.x;
    int b  = blockIdx.z;
    int q0 = blockIdx.y * 16, k0 = blockIdx.x * 16;

    {
        int i = tid >> 3, p = tid & 7;
        WgS2[i][p] = pack2(Wg[(2*p)*64 + i],      Wg[(2*p+1)*64 + i]);
        WgC2[i][p] = pack2(Wg[(2*p)*64 + 32 + i], Wg[(2*p+1)*64 + 32 + i]);
    }
    if (tid < 16) {
        bgs[tid] = bg[tid];
        #pragma unroll
        for (int j = 0; j < 6; j++) qf[tid][j] = g_boxf[(b*NN + q0 + tid)*6 + j];
    } else if (tid < 32) {
        int t = tid - 16;
        #pragma unroll
        for (int j = 0; j < 6; j++) kf[t][j] = g_boxf[(b*NN + k0 + t)*6 + j];
    }
    __syncthreads();

    int ty = tid >> 4, tx = tid & 15;
    float pos[4];
    pos[0] = __logf(fmaxf(fabsf(qf[ty][0] - kf[tx][0]) * qf[ty][2], 1e-3f));
    pos[1] = __logf(fmaxf(fabsf(qf[ty][1] - kf[tx][1]) * qf[ty][3], 1e-3f));
    pos[2] = qf[ty][4] - kf[tx][4];
    pos[3] = qf[ty][5] - kf[tx][5];

    unsigned long long acc2[8];
    #pragma unroll
    for (int p = 0; p < 8; p++) acc2[p] = pack2(bgs[2*p], bgs[2*p+1]);

    const float dm[8] = {1.0f, 0.42169650f, 0.17782794f, 0.07498942f,
                         0.03162278f, 0.01333521f, 0.00562341f, 0.00237137f};
    #pragma unroll
    for (int c = 0; c < 4; c++) {
        float p100 = 100.0f * pos[c];
        #pragma unroll
        for (int f = 0; f < 8; f++) {
            float s, co;
            __sincosf(p100 * dm[f], &s, &co);
            unsigned long long s2 = pack2(s, s), c2 = pack2(co, co);
            int idx = c*8 + f;
            #pragma unroll
            for (int p = 0; p < 8; p++) {
                unsigned long long t = fma2(c2, WgC2[idx][p], acc2[p]);
                acc2[p] = fma2(s2, WgS2[idx][p], t);
            }
        }
    }
    int q = q0 + ty, k = k0 + tx;
    #pragma unroll
    for (int p = 0; p < 8; p++) {
        float x, y;
        unpack2(acc2[p], x, y);
        g_s[(((size_t)b*HH + 2*p  )*NN + q)*NN + k] = __logf(fmaxf(x, 1e-6f));
        g_s[(((size_t)b*HH + 2*p+1)*NN + q)*NN + k] = __logf(fmaxf(y, 1e-6f));
    }
}

// ============================================================
// fp16 GEMM, 128x128 CTA tile, 8 warps of 32x64, KTILE=64 halves,
// 3-stage cp.async, ldmatrix b16, mma m16n8k16.
// MODE 0: QKV (A=g_acth[z], B=g_wh[z], rounded scatter to g_q/g_k/g_v)
// MODE 1: O-proj (A=g_o1h, B=g_wh[3], dst=Cout)
// ============================================================
#define HST 72                              // smem row stride in halves (64 + pad 8)
#define HTILE (128*HST)                     // halves per matrix per stage
#define HSMEM (3 * 2 * HTILE * 2)           // 110592 B

template<int MODE>
__global__ void __launch_bounds__(256, 2) gemm_tc(
    const float* __restrict__ b0p, const float* __restrict__ b1p,
    const float* __restrict__ b2p, float* __restrict__ Cout)
{
    constexpr int KD  = DMODEL;
    constexpr int NIT = KD / 64;            // 16 chunks of 64 halves
    extern __shared__ __half hsm[];

    int t = threadIdx.x;
    int m0 = blockIdx.y * 128, n0 = blockIdx.x * 128;
    int z = blockIdx.z;

    const __half *A, *B;
    const float *bias;
    if (MODE == 0) {
        A = g_acth + (size_t)z*(BB*NN*DMODEL);
        B = g_wh   + (size_t)z*(DMODEL*DMODEL);
        bias = (z == 0) ? b0p : (z == 1) ? b1p : b2p;
    } else {
        A = g_o1h;
        B = g_wh + 3*(size_t)(DMODEL*DMODEL);
        bias = b0p;
    }

    // per-thread load slots: 4 chunks of A + 4 of B per stage
    // (per matrix per stage: 128 rows x 64 halves = 1024 x 16B; 256 thr x 4)
    int lrows[4], lhc[4];
    #pragma unroll
    for (int i = 0; i < 4; i++) {
        int idx = t + i*256;
        lrows[i] = idx >> 3;
        lhc[i]   = (idx & 7) * 8;
    }
    unsigned sbase = smaddr(hsm);

    int w = t >> 5, l = t & 31;
    int wm = w & 3, wn = w >> 2;            // 8 warps: 4 (m) x 2 (n), 32x64 tiles
    int lj   = l & 7;
    int goff = ((l >> 3) & 1) * 8 + lj;     // row-within-16 for ldsm groups
    int khq  = (l >> 4) * 8;                // k-half offset (0 or 8)

    float acc[2][8][4];
    #pragma unroll
    for (int i = 0; i < 2; i++)
        #pragma unroll
        for (int j = 0; j < 8; j++)
            #pragma unroll
            for (int k = 0; k < 4; k++) acc[i][j][k] = 0.0f;

    // prologue: chunks 0,1 -> stages 0,1
    #pragma unroll
    for (int p = 0; p < 2; p++) {
        unsigned ab = sbase + (unsigned)(p*2*HTILE)*2u;
        #pragma unroll
        for (int i = 0; i < 4; i++) {
            cpa16(ab + (lrows[i]*HST + lhc[i])*2u,
                  A + (size_t)(m0 + lrows[i])*KD + p*64 + lhc[i]);
            cpa16(ab + (HTILE + lrows[i]*HST + lhc[i])*2u,
                  B + (size_t)(n0 + lrows[i])*KD + p*64 + lhc[i]);
        }
        cp_commit();
    }

    for (int j = 0; j < NIT; j++) {
        cp_wait1();
        __syncthreads();
        if (j + 2 < NIT) {
            int s = (j + 2) % 3;
            unsigned ab = sbase + (unsigned)(s*2*HTILE)*2u;
            int kb = (j + 2) * 64;
            #pragma unroll
            for (int i = 0; i < 4; i++) {
                cpa16(ab + (lrows[i]*HST + lhc[i])*2u,
                      A + (size_t)(m0 + lrows[i])*KD + kb + lhc[i]);
                cpa16(ab + (HTILE + lrows[i]*HST + lhc[i])*2u,
                      B + (size_t)(n0 + lrows[i])*KD + kb + lhc[i]);
            }
        }
        cp_commit();

        int s = j % 3;
        const __half* As = hsm + s*2*HTILE;
        const __half* Bs = As + HTILE;
        #pragma unroll
        for (int kc = 0; kc < 4; kc++) {           // 4 x k16
            unsigned a[2][4];
            #pragma unroll
            for (int mf = 0; mf < 2; mf++)
                ldsm4(a[mf][0], a[mf][1], a[mf][2], a[mf][3],
                      smaddr(&As[(wm*32 + mf*16 + goff)*HST + kc*16 + khq]));
            #pragma unroll
            for (int nt = 0; nt < 4; nt++) {       // 4 x n16
                unsigned bb[4];
                ldsm4(bb[0], bb[1], bb[2], bb[3],
                      smaddr(&Bs[(wn*64 + nt*16 + goff)*HST + kc*16 + khq]));
                #pragma unroll
                for (int mf = 0; mf < 2; mf++) {
                    mma16h(acc[mf][2*nt],   a[mf], bb[0], bb[2]);
                    mma16h(acc[mf][2*nt+1], a[mf], bb[1], bb[3]);
                }
            }
        }
    }

    // epilogue
    #pragma unroll
    for (int mf = 0; mf < 2; mf++) {
        #pragma unroll
        for (int nf = 0; nf < 8; nf++) {
            int col = n0 + wn*64 + nf*8 + 2*(l & 3);
            float2 b2 = *(const float2*)(bias + col);
            #pragma unroll
            for (int rr = 0; rr < 2; rr++) {
                int row = m0 + wm*32 + mf*16 + rr*8 + (l >> 2);
                float v0 = acc[mf][nf][rr*2 + 0] + b2.x;
                float v1 = acc[mf][nf][rr*2 + 1] + b2.y;
                if (MODE == 0) {
                    int h = col >> 6, d = col & 63;
                    int bq = row >> 9, ntok = row & (NN-1);
                    float* dstp = (z == 0) ? g_q : (z == 1) ? g_k : g_v;
                    *(float2*)&dstp[(((size_t)bq*HH + h)*NN + ntok)*DK + d] =
                        make_float2(r2(v0), r2(v1));
                } else {
                    *(float2*)&Cout[(size_t)row*DMODEL + col] = make_float2(v0, v1);
                }
            }
        }
    }
}

// ============================================================
// fused attention: S = bias + (Q/8)Kt, online softmax, O += P V
// (tf32 path, unchanged except fp16 output for O-proj)
// ============================================================
#define KS_ST 68
#define VS_ST 72
#define PS_ST 68
#define FUSED_SMEM ((2*64*KS_ST + 2*64*VS_ST + 128*PS_ST) * 4)

__global__ void __launch_bounds__(256, 2) fused_attn() {
    extern __shared__ float smf[];
    float* KsB = smf;
    float* VsB = smf + 2*64*KS_ST;
    float* Ps  = VsB + 2*64*VS_ST;

    int t = threadIdx.x;
    int bh = blockIdx.y;
    int q0 = blockIdx.x * 128;
    const float* Qg = g_q + ((size_t)bh*NN + q0)*DK;
    const float* Kg = g_k + (size_t)bh*NN*DK;
    const float* Vg = g_v + (size_t)bh*NN*DK;
    const float* Sg = g_s + (size_t)bh*NN*NN;

    int w = t >> 5, l = t & 31;
    int r0 = l >> 2, c0 = l & 3;
    int qrow = w*16 + r0;
    int lj   = l & 7;
    int aRow = ((l >> 3) & 1) * 8 + lj;
    int aCol = (l >> 4) * 4;
    int bRow = (l >> 4) * 8 + lj;
    int bCol = ((l >> 3) & 1) * 4;

    #pragma unroll
    for (int i = 0; i < 8; i++) {
        int idx = t + i*256;
        int row = idx >> 4, col = (idx & 15) * 4;
        cpa16(smaddr(Ps + row*PS_ST + col), Qg + row*DK + col);
    }
    #pragma unroll
    for (int i = 0; i < 4; i++) {
        int idx = t + i*256;
        int row = idx >> 4, col = (idx & 15) * 4;
        cpa16(smaddr(KsB + row*KS_ST + col), Kg + row*DK + col);
        cpa16(smaddr(VsB + row*VS_ST + col), Vg + row*DK + col);
    }
    cp_commit();
    cp_wait0();
    __syncthreads();

    unsigned qa[8][4];
    #pragma unroll
    for (int kc = 0; kc < 8; kc++) {
        qa[kc][0] = __float_as_uint(0.125f * Ps[qrow*PS_ST     + kc*8 + c0]);
        qa[kc][1] = __float_as_uint(0.125f * Ps[(qrow+8)*PS_ST + kc*8 + c0]);
        qa[kc][2] = __float_as_uint(0.125f * Ps[qrow*PS_ST     + kc*8 + c0 + 4]);
        qa[kc][3] = __float_as_uint(0.125f * Ps[(qrow+8)*PS_ST + kc*8 + c0 + 4]);
    }

    float Oa[8][4];
    #pragma unroll
    for (int nf = 0; nf < 8; nf++)
        #pragma unroll
        for (int k = 0; k < 4; k++) Oa[nf][k] = 0.0f;
    float m0v = -INFINITY, m1v = -INFINITY, l0v = 0.0f, l1v = 0.0f;

    const int NT = NN / 64;
    for (int j = 0; j < NT; j++) {
        if (j > 0) cp_wait0();
        __syncthreads();
        if (j + 1 < NT) {
            int nb = (j + 1) & 1;
            float* Ksn = KsB + nb*64*KS_ST;
            float* Vsn = VsB + nb*64*VS_ST;
            #pragma unroll
            for (int i = 0; i < 4; i++) {
                int idx = t + i*256;
                int row = idx >> 4, col = (idx & 15) * 4;
                cpa16(smaddr(Ksn + row*KS_ST + col), Kg + ((j+1)*64 + row)*DK + col);
                cpa16(smaddr(Vsn + row*VS_ST + col), Vg + ((j+1)*64 + row)*DK + col);
            }
        }
        cp_commit();

        const float* Ks = KsB + (j & 1)*64*KS_ST;
        const float* Vs = VsB + (j & 1)*64*VS_ST;

        float acc[8][4];
        {
            const float* br0 = Sg + (size_t)(q0 + qrow)*NN + j*64;
            const float* br1 = br0 + 8*NN;
            #pragma unroll
            for (int nf = 0; nf < 8; nf++) {
                float2 t0 = *(const float2*)(br0 + nf*8 + 2*c0);
                float2 t1 = *(const float2*)(br1 + nf*8 + 2*c0);
                acc[nf][0] = t0.x; acc[nf][1] = t0.y;
                acc[nf][2] = t1.x; acc[nf][3] = t1.y;
            }
        }
        #pragma unroll
        for (int kc = 0; kc < 8; kc++) {
            #pragma unroll
            for (int p = 0; p < 4; p++) {
                unsigned bb[4];
                ldsm4(bb[0], bb[1], bb[2], bb[3],
                      smaddr(&Ks[(p*16 + bRow)*KS_ST + kc*8 + bCol]));
                mma8(acc[2*p],   qa[kc], bb);
                mma8(acc[2*p+1], qa[kc], bb + 2);
            }
        }

        float mx0 = -INFINITY, mx1 = -INFINITY;
        #pragma unroll
        for (int nf = 0; nf < 8; nf++) {
            mx0 = fmaxf(mx0, fmaxf(acc[nf][0], acc[nf][1]));
            mx1 = fmaxf(mx1, fmaxf(acc[nf][2], acc[nf][3]));
        }
        #pragma unroll
        for (int o = 1; o <= 2; o <<= 1) {
            mx0 = fmaxf(mx0, __shfl_xor_sync(0xffffffffu, mx0, o));
            mx1 = fmaxf(mx1, __shfl_xor_sync(0xffffffffu, mx1, o));
        }
        float mn0 = fmaxf(m0v, mx0), mn1 = fmaxf(m1v, mx1);
        float sc0 = __expf(m0v - mn0), sc1 = __expf(m1v - mn1);
        m0v = mn0; m1v = mn1;
        float s0 = 0.0f, s1 = 0.0f;
        #pragma unroll
        for (int nf = 0; nf < 8; nf++) {
            acc[nf][0] = __expf(acc[nf][0] - mn0);
            acc[nf][1] = __expf(acc[nf][1] - mn0);
            acc[nf][2] = __expf(acc[nf][2] - mn1);
            acc[nf][3] = __expf(acc[nf][3] - mn1);
            s0 += acc[nf][0] + acc[nf][1];
            s1 += acc[nf][2] + acc[nf][3];
        }
        #pragma unroll
        for (int o = 1; o <= 2; o <<= 1) {
            s0 += __shfl_xor_sync(0xffffffffu, s0, o);
            s1 += __shfl_xor_sync(0xffffffffu, s1, o);
        }
        l0v = l0v * sc0 + s0;
        l1v = l1v * sc1 + s1;
        #pragma unroll
        for (int nf = 0; nf < 8; nf++) {
            Oa[nf][0] *= sc0; Oa[nf][1] *= sc0;
            Oa[nf][2] *= sc1; Oa[nf][3] *= sc1;
        }

        #pragma unroll
        for (int nf = 0; nf < 8; nf++) {
            *(float2*)&Ps[qrow*PS_ST     + nf*8 + 2*c0] =
                make_float2(r2(acc[nf][0]), r2(acc[nf][1]));
            *(float2*)&Ps[(qrow+8)*PS_ST + nf*8 + 2*c0] =
                make_float2(r2(acc[nf][2]), r2(acc[nf][3]));
        }
        __syncwarp();
        #pragma unroll
        for (int kc = 0; kc < 8; kc++) {
            unsigned a4[4];
            ldsm4(a4[0], a4[1], a4[2], a4[3],
                  smaddr(&Ps[(w*16 + aRow)*PS_ST + kc*8 + aCol]));
            #pragma unroll
            for (int nf = 0; nf < 8; nf++) {
                unsigned b[2];
                b[0] = __float_as_uint(Vs[(kc*8 + c0    )*VS_ST + r0 + nf*8]);
                b[1] = __float_as_uint(Vs[(kc*8 + c0 + 4)*VS_ST + r0 + nf*8]);
                mma8(Oa[nf], a4, b);
            }
        }
        __syncwarp();
    }

    // epilogue: O /= l, write fp16 to g_o1h (feeds fp16 O-proj)
    float inv0 = 1.0f / l0v, inv1 = 1.0f / l1v;
    int b = bh >> 4, h = bh & 15;
    __half* O0 = g_o1h + ((size_t)b*NN + q0 + qrow)*DMODEL + h*DK;
    __half* O1 = O0 + 8*DMODEL;
    #pragma unroll
    for (int nf = 0; nf < 8; nf++) {
        *(__half2*)(O0 + nf*8 + 2*c0) = __floats2half2_rn(Oa[nf][0]*inv0, Oa[nf][1]*inv0);
        *(__half2*)(O1 + nf*8 + 2*c0) = __floats2half2_rn(Oa[nf][2]*inv1, Oa[nf][3]*inv1);
    }
}

// ============================================================
extern "C" void kernel_launch(void* const* d_in, const int* in_sizes, int n_in,
                              void* d_out, int out_size) {
    const float* queries = (const float*)d_in[0];
    const float* keys    = (const float*)d_in[1];
    const float* values  = (const float*)d_in[2];
    const float* boxes   = (const float*)d_in[3];
    const float* Wq = (const float*)d_in[4];
    const float* bq = (const float*)d_in[5];
    const float* Wk = (const float*)d_in[6];
    const float* bk = (const float*)d_in[7];
    const float* Wv = (const float*)d_in[8];
    const float* bv = (const float*)d_in[9];
    const float* Wo = (const float*)d_in[10];
    const float* bo = (const float*)d_in[11];
    const float* Wg = (const float*)d_in[12];
    const float* bg = (const float*)d_in[13];
    float* out = (float*)d_out;

    cudaFuncSetAttribute(gemm_tc<0>, cudaFuncAttributeMaxDynamicSharedMemorySize, HSMEM);
    cudaFuncSetAttribute(gemm_tc<1>, cudaFuncAttributeMaxDynamicSharedMemorySize, HSMEM);
    cudaFuncSetAttribute(fused_attn, cudaFuncAttributeMaxDynamicSharedMemorySize,
                         FUSED_SMEM);

    boxfeat_kernel<<<16, 256>>>(boxes);
    prep_kernel<<<dim3(4096, 7), 256>>>(queries, keys, values, Wq, Wk, Wv, Wo);
    geom_kernel<<<dim3(32, 32, 8), 256>>>(Wg, bg);
    gemm_tc<0><<<dim3(8, 32, 3), 256, HSMEM>>>(bq, bk, bv, nullptr);
    fused_attn<<<dim3(4, 128), 256, FUSED_SMEM>>>();
    gemm_tc<1><<<dim3(8, 32, 1), 256, HSMEM>>>(bo, nullptr, nullptr, out);
}

// round 14
// speedup vs baseline: 1.3535x; 1.0836x over previous
#include <cuda_runtime.h>
#include <cuda_fp16.h>
#include <math.h>

#define BB 8
#define NN 512
#define DMODEL 1024
#define HH 16
#define DK 64

// ---- static scratch ----
__device__ __half g_qh[BB*HH*NN*DK];      // fp16, pre-scaled by 1/8
__device__ __half g_kh[BB*HH*NN*DK];
__device__ __half g_vh[BB*HH*NN*DK];
__device__ float g_s[BB*HH*NN*NN];        // geometry bias (log g), fp32
__device__ __half g_o1h[BB*NN*DMODEL];    // attn output, fp16 (feeds O-proj)
__device__ float g_boxf[BB*NN*6];
__device__ __half g_acth[3*BB*NN*DMODEL]; // fp16 activations (q,k,v inputs)
__device__ __half g_wh[4*DMODEL*DMODEL];  // fp16 weights Wq,Wk,Wv,Wo

// ---- helpers ----
__device__ __forceinline__ void mma16h(float* c, const unsigned* a,
                                       unsigned b0, unsigned b1) {
    asm volatile("mma.sync.aligned.m16n8k16.row.col.f32.f16.f16.f32 "
        "{%0,%1,%2,%3},{%4,%5,%6,%7},{%8,%9},{%0,%1,%2,%3};"
        : "+f"(c[0]), "+f"(c[1]), "+f"(c[2]), "+f"(c[3])
        : "r"(a[0]), "r"(a[1]), "r"(a[2]), "r"(a[3]), "r"(b0), "r"(b1));
}
__device__ __forceinline__ void ldsm4(unsigned& r0, unsigned& r1, unsigned& r2v,
                                      unsigned& r3, unsigned a) {
    asm volatile("ldmatrix.sync.aligned.m8n8.x4.shared.b16 {%0,%1,%2,%3}, [%4];"
        : "=r"(r0), "=r"(r1), "=r"(r2v), "=r"(r3) : "r"(a));
}
__device__ __forceinline__ void ldsm4t(unsigned& r0, unsigned& r1, unsigned& r2v,
                                       unsigned& r3, unsigned a) {
    asm volatile("ldmatrix.sync.aligned.m8n8.x4.trans.shared.b16 {%0,%1,%2,%3}, [%4];"
        : "=r"(r0), "=r"(r1), "=r"(r2v), "=r"(r3) : "r"(a));
}
__device__ __forceinline__ void cpa16(unsigned dst, const void* src) {
    asm volatile("cp.async.cg.shared.global [%0], [%1], 16;" :: "r"(dst), "l"(src));
}
__device__ __forceinline__ void cp_commit() {
    asm volatile("cp.async.commit_group;" ::: "memory");
}
__device__ __forceinline__ void cp_wait1() {
    asm volatile("cp.async.wait_group 1;" ::: "memory");
}
__device__ __forceinline__ void cp_wait0() {
    asm volatile("cp.async.wait_group 0;" ::: "memory");
}
__device__ __forceinline__ unsigned smaddr(const void* p) {
    return (unsigned)__cvta_generic_to_shared(p);
}
__device__ __forceinline__ unsigned long long pack2(float x, float y) {
    unsigned long long r; asm("mov.b64 %0,{%1,%2};" : "=l"(r) : "f"(x), "f"(y)); return r;
}
__device__ __forceinline__ void unpack2(unsigned long long v, float& x, float& y) {
    asm("mov.b64 {%0,%1},%2;" : "=f"(x), "=f"(y) : "l"(v));
}
__device__ __forceinline__ unsigned long long fma2(unsigned long long a, unsigned long long b,
                                                   unsigned long long c) {
    unsigned long long d;
    asm("fma.rn.f32x2 %0,%1,%2,%3;" : "=l"(d) : "l"(a), "l"(b), "l"(c)); return d;
}

// ============================================================
// box features
// ============================================================
__global__ void boxfeat_kernel(const float* __restrict__ boxes) {
    int i = blockIdx.x * blockDim.x + threadIdx.x;
    if (i >= BB*NN) return;
    float4 bx = ((const float4*)boxes)[i];
    float cx = 0.5f * (bx.x + bx.z);
    float cy = 0.5f * (bx.y + bx.w);
    float w  = bx.z - bx.x + 1.0f;
    float h  = bx.w - bx.y + 1.0f;
    float* o = &g_boxf[i*6];
    o[0] = cx; o[1] = cy;
    o[2] = 1.0f / w; o[3] = 1.0f / h;
    o[4] = __logf(w); o[5] = __logf(h);
}

// ============================================================
// convert activations + weights to fp16
// ============================================================
__global__ void prep_kernel(const float* __restrict__ q, const float* __restrict__ k,
                            const float* __restrict__ v, const float* __restrict__ wq,
                            const float* __restrict__ wk, const float* __restrict__ wv,
                            const float* __restrict__ wo) {
    int z = blockIdx.y;
    const float* src = (z==0)?q:(z==1)?k:(z==2)?v:(z==3)?wq:(z==4)?wk:(z==5)?wv:wo;
    __half* dst = (z < 3) ? g_acth + (size_t)z*(BB*NN*DMODEL)
                          : g_wh + (size_t)(z-3)*(DMODEL*DMODEL);
    int n4 = (z < 3) ? (BB*NN*DMODEL/4) : (DMODEL*DMODEL/4);
    int i = blockIdx.x*256 + threadIdx.x;
    if (i < n4) {
        float4 a = ((const float4*)src)[i];
        ((__half2*)dst)[2*i]   = __floats2half2_rn(a.x, a.y);
        ((__half2*)dst)[2*i+1] = __floats2half2_rn(a.z, a.w);
    }
}

// ============================================================
// geometry bias, packed f32x2 over head pairs
// ============================================================
__global__ void __launch_bounds__(256) geom_kernel(const float* __restrict__ Wg,
                                                   const float* __restrict__ bg) {
    __shared__ unsigned long long WgS2[32][8];
    __shared__ unsigned long long WgC2[32][8];
    __shared__ float qf[16][6];
    __shared__ float kf[16][6];
    __shared__ float bgs[16];
    int tid = threadIdx.x;
    int b  = blockIdx.z;
    int q0 = blockIdx.y * 16, k0 = blockIdx.x * 16;

    {
        int i = tid >> 3, p = tid & 7;
        WgS2[i][p] = pack2(Wg[(2*p)*64 + i],      Wg[(2*p+1)*64 + i]);
        WgC2[i][p] = pack2(Wg[(2*p)*64 + 32 + i], Wg[(2*p+1)*64 + 32 + i]);
    }
    if (tid < 16) {
        bgs[tid] = bg[tid];
        #pragma unroll
        for (int j = 0; j < 6; j++) qf[tid][j] = g_boxf[(b*NN + q0 + tid)*6 + j];
    } else if (tid < 32) {
        int t = tid - 16;
        #pragma unroll
        for (int j = 0; j < 6; j++) kf[t][j] = g_boxf[(b*NN + k0 + t)*6 + j];
    }
    __syncthreads();

    int ty = tid >> 4, tx = tid & 15;
    float pos[4];
    pos[0] = __logf(fmaxf(fabsf(qf[ty][0] - kf[tx][0]) * qf[ty][2], 1e-3f));
    pos[1] = __logf(fmaxf(fabsf(qf[ty][1] - kf[tx][1]) * qf[ty][3], 1e-3f));
    pos[2] = qf[ty][4] - kf[tx][4];
    pos[3] = qf[ty][5] - kf[tx][5];

    unsigned long long acc2[8];
    #pragma unroll
    for (int p = 0; p < 8; p++) acc2[p] = pack2(bgs[2*p], bgs[2*p+1]);

    const float dm[8] = {1.0f, 0.42169650f, 0.17782794f, 0.07498942f,
                         0.03162278f, 0.01333521f, 0.00562341f, 0.00237137f};
    #pragma unroll
    for (int c = 0; c < 4; c++) {
        float p100 = 100.0f * pos[c];
        #pragma unroll
        for (int f = 0; f < 8; f++) {
            float s, co;
            __sincosf(p100 * dm[f], &s, &co);
            unsigned long long s2 = pack2(s, s), c2 = pack2(co, co);
            int idx = c*8 + f;
            #pragma unroll
            for (int p = 0; p < 8; p++) {
                unsigned long long t = fma2(c2, WgC2[idx][p], acc2[p]);
                acc2[p] = fma2(s2, WgS2[idx][p], t);
            }
        }
    }
    int q = q0 + ty, k = k0 + tx;
    #pragma unroll
    for (int p = 0; p < 8; p++) {
        float x, y;
        unpack2(acc2[p], x, y);
        g_s[(((size_t)b*HH + 2*p  )*NN + q)*NN + k] = __logf(fmaxf(x, 1e-6f));
        g_s[(((size_t)b*HH + 2*p+1)*NN + q)*NN + k] = __logf(fmaxf(y, 1e-6f));
    }
}

// ============================================================
// fp16 GEMM, 128x128 CTA tile, 8 warps of 32x64, KTILE=64 halves,
// 3-stage cp.async, ldmatrix b16, mma m16n8k16.
// MODE 0: QKV (A=g_acth[z], B=g_wh[z], fp16 scatter to g_qh/g_kh/g_vh,
//         z==0 scaled by 1/8)
// MODE 1: O-proj (A=g_o1h, B=g_wh[3], dst=Cout, fp32)
// ============================================================
#define HST 72                              // smem row stride in halves
#define HTILE (128*HST)
#define HSMEM (3 * 2 * HTILE * 2)           // 110592 B

template<int MODE>
__global__ void __launch_bounds__(256, 2) gemm_tc(
    const float* __restrict__ b0p, const float* __restrict__ b1p,
    const float* __restrict__ b2p, float* __restrict__ Cout)
{
    constexpr int KD  = DMODEL;
    constexpr int NIT = KD / 64;
    extern __shared__ __half hsm[];

    int t = threadIdx.x;
    int m0 = blockIdx.y * 128, n0 = blockIdx.x * 128;
    int z = blockIdx.z;

    const __half *A, *B;
    const float *bias;
    if (MODE == 0) {
        A = g_acth + (size_t)z*(BB*NN*DMODEL);
        B = g_wh   + (size_t)z*(DMODEL*DMODEL);
        bias = (z == 0) ? b0p : (z == 1) ? b1p : b2p;
    } else {
        A = g_o1h;
        B = g_wh + 3*(size_t)(DMODEL*DMODEL);
        bias = b0p;
    }

    int lrows[4], lhc[4];
    #pragma unroll
    for (int i = 0; i < 4; i++) {
        int idx = t + i*256;
        lrows[i] = idx >> 3;
        lhc[i]   = (idx & 7) * 8;
    }
    unsigned sbase = smaddr(hsm);

    int w = t >> 5, l = t & 31;
    int wm = w & 3, wn = w >> 2;
    int lj   = l & 7;
    int goff = ((l >> 3) & 1) * 8 + lj;
    int khq  = (l >> 4) * 8;

    float acc[2][8][4];
    #pragma unroll
    for (int i = 0; i < 2; i++)
        #pragma unroll
        for (int j = 0; j < 8; j++)
            #pragma unroll
            for (int k = 0; k < 4; k++) acc[i][j][k] = 0.0f;

    #pragma unroll
    for (int p = 0; p < 2; p++) {
        unsigned ab = sbase + (unsigned)(p*2*HTILE)*2u;
        #pragma unroll
        for (int i = 0; i < 4; i++) {
            cpa16(ab + (lrows[i]*HST + lhc[i])*2u,
                  A + (size_t)(m0 + lrows[i])*KD + p*64 + lhc[i]);
            cpa16(ab + (HTILE + lrows[i]*HST + lhc[i])*2u,
                  B + (size_t)(n0 + lrows[i])*KD + p*64 + lhc[i]);
        }
        cp_commit();
    }

    for (int j = 0; j < NIT; j++) {
        cp_wait1();
        __syncthreads();
        if (j + 2 < NIT) {
            int s = (j + 2) % 3;
            unsigned ab = sbase + (unsigned)(s*2*HTILE)*2u;
            int kb = (j + 2) * 64;
            #pragma unroll
            for (int i = 0; i < 4; i++) {
                cpa16(ab + (lrows[i]*HST + lhc[i])*2u,
                      A + (size_t)(m0 + lrows[i])*KD + kb + lhc[i]);
                cpa16(ab + (HTILE + lrows[i]*HST + lhc[i])*2u,
                      B + (size_t)(n0 + lrows[i])*KD + kb + lhc[i]);
            }
        }
        cp_commit();

        int s = j % 3;
        const __half* As = hsm + s*2*HTILE;
        const __half* Bs = As + HTILE;
        #pragma unroll
        for (int kc = 0; kc < 4; kc++) {
            unsigned a[2][4];
            #pragma unroll
            for (int mf = 0; mf < 2; mf++)
                ldsm4(a[mf][0], a[mf][1], a[mf][2], a[mf][3],
                      smaddr(&As[(wm*32 + mf*16 + goff)*HST + kc*16 + khq]));
            #pragma unroll
            for (int nt = 0; nt < 4; nt++) {
                unsigned bb[4];
                ldsm4(bb[0], bb[1], bb[2], bb[3],
                      smaddr(&Bs[(wn*64 + nt*16 + goff)*HST + kc*16 + khq]));
                #pragma unroll
                for (int mf = 0; mf < 2; mf++) {
                    mma16h(acc[mf][2*nt],   a[mf], bb[0], bb[2]);
                    mma16h(acc[mf][2*nt+1], a[mf], bb[1], bb[3]);
                }
            }
        }
    }

    // epilogue
    float qsc = (MODE == 0 && z == 0) ? 0.125f : 1.0f;
    #pragma unroll
    for (int mf = 0; mf < 2; mf++) {
        #pragma unroll
        for (int nf = 0; nf < 8; nf++) {
            int col = n0 + wn*64 + nf*8 + 2*(l & 3);
            float2 b2 = *(const float2*)(bias + col);
            #pragma unroll
            for (int rr = 0; rr < 2; rr++) {
                int row = m0 + wm*32 + mf*16 + rr*8 + (l >> 2);
                float v0 = acc[mf][nf][rr*2 + 0] + b2.x;
                float v1 = acc[mf][nf][rr*2 + 1] + b2.y;
                if (MODE == 0) {
                    int h = col >> 6, d = col & 63;
                    int bq = row >> 9, ntok = row & (NN-1);
                    __half* dstp = (z == 0) ? g_qh : (z == 1) ? g_kh : g_vh;
                    *(__half2*)&dstp[(((size_t)bq*HH + h)*NN + ntok)*DK + d] =
                        __floats2half2_rn(v0*qsc, v1*qsc);
                } else {
                    *(float2*)&Cout[(size_t)row*DMODEL + col] = make_float2(v0, v1);
                }
            }
        }
    }
}

// ============================================================
// fused attention, fp16 MMAs: S = bias + Q'Kt (Q' pre-scaled),
// online softmax, O += P V.  CTA: 128 q x one bh, 8 warps of 16 q.
// ============================================================
#define QST 72
#define KST 72
#define VST 72
#define FUSED_SMEM ((2*64*KST + 2*64*VST + 128*QST) * 2)

__global__ void __launch_bounds__(256, 2) fused_attn() {
    extern __shared__ __half smh[];
    __half* KsB = smh;                      // [2][64][KST]
    __half* VsB = smh + 2*64*KST;           // [2][64][VST]
    __half* Ps  = VsB + 2*64*VST;           // [128][QST]  (Q, then P)

    int t = threadIdx.x;
    int bh = blockIdx.y;
    int q0 = blockIdx.x * 128;
    const __half* Qg = g_qh + ((size_t)bh*NN + q0)*DK;
    const __half* Kg = g_kh + (size_t)bh*NN*DK;
    const __half* Vg = g_vh + (size_t)bh*NN*DK;
    const float*  Sg = g_s  + (size_t)bh*NN*NN;

    int w = t >> 5, l = t & 31;
    int r0 = l >> 2, c0 = l & 3;
    int qrow = w*16 + r0;
    int lj   = l & 7;
    int goff = ((l >> 3) & 1) * 8 + lj;
    int khq  = (l >> 4) * 8;

    // prologue: Q into Ps (4 cpa16/thr), K/V tile 0 (2 each)
    #pragma unroll
    for (int i = 0; i < 4; i++) {
        int idx = t + i*256;
        int row = idx >> 3, col = (idx & 7) * 8;
        cpa16(smaddr(Ps + row*QST + col), Qg + row*DK + col);
    }
    #pragma unroll
    for (int i = 0; i < 2; i++) {
        int idx = t + i*256;
        int row = idx >> 3, col = (idx & 7) * 8;
        cpa16(smaddr(KsB + row*KST + col), Kg + row*DK + col);
        cpa16(smaddr(VsB + row*VST + col), Vg + row*DK + col);
    }
    cp_commit();
    cp_wait0();
    __syncthreads();

    // Q fragments (4 k16 chunks)
    unsigned qa[4][4];
    #pragma unroll
    for (int kc = 0; kc < 4; kc++)
        ldsm4(qa[kc][0], qa[kc][1], qa[kc][2], qa[kc][3],
              smaddr(&Ps[(w*16 + goff)*QST + kc*16 + khq]));
    __syncthreads();    // Ps reused for P below

    float Oa[8][4];
    #pragma unroll
    for (int nf = 0; nf < 8; nf++)
        #pragma unroll
        for (int k = 0; k < 4; k++) Oa[nf][k] = 0.0f;
    float m0v = -INFINITY, m1v = -INFINITY, l0v = 0.0f, l1v = 0.0f;

    const int NT = NN / 64;
    for (int j = 0; j < NT; j++) {
        if (j > 0) {
            cp_wait0();
            __syncthreads();
        }
        if (j + 1 < NT) {
            int nb = (j + 1) & 1;
            __half* Ksn = KsB + nb*64*KST;
            __half* Vsn = VsB + nb*64*VST;
            #pragma unroll
            for (int i = 0; i < 2; i++) {
                int idx = t + i*256;
                int row = idx >> 3, col = (idx & 7) * 8;
                cpa16(smaddr(Ksn + row*KST + col), Kg + ((j+1)*64 + row)*DK + col);
                cpa16(smaddr(Vsn + row*VST + col), Vg + ((j+1)*64 + row)*DK + col);
            }
        }
        cp_commit();

        const __half* Ks = KsB + (j & 1)*64*KST;
        const __half* Vs = VsB + (j & 1)*64*VST;

        // S acc init = bias tile from g_s
        float acc[8][4];
        {
            const float* br0 = Sg + (size_t)(q0 + qrow)*NN + j*64;
            const float* br1 = br0 + 8*NN;
            #pragma unroll
            for (int nf = 0; nf < 8; nf++) {
                float2 t0 = *(const float2*)(br0 + nf*8 + 2*c0);
                float2 t1 = *(const float2*)(br1 + nf*8 + 2*c0);
                acc[nf][0] = t0.x; acc[nf][1] = t0.y;
                acc[nf][2] = t1.x; acc[nf][3] = t1.y;
            }
        }
        // S += Q' K^T  (K b-operand: non-trans ldsm, k-contiguous)
        #pragma unroll
        for (int kc = 0; kc < 4; kc++) {
            #pragma unroll
            for (int nt = 0; nt < 4; nt++) {
                unsigned bb[4];
                ldsm4(bb[0], bb[1], bb[2], bb[3],
                      smaddr(&Ks[(nt*16 + goff)*KST + kc*16 + khq]));
                mma16h(acc[2*nt],   qa[kc], bb[0], bb[2]);
                mma16h(acc[2*nt+1], qa[kc], bb[1], bb[3]);
            }
        }

        // online softmax
        float mx0 = -INFINITY, mx1 = -INFINITY;
        #pragma unroll
        for (int nf = 0; nf < 8; nf++) {
            mx0 = fmaxf(mx0, fmaxf(acc[nf][0], acc[nf][1]));
            mx1 = fmaxf(mx1, fmaxf(acc[nf][2], acc[nf][3]));
        }
        #pragma unroll
        for (int o = 1; o <= 2; o <<= 1) {
            mx0 = fmaxf(mx0, __shfl_xor_sync(0xffffffffu, mx0, o));
            mx1 = fmaxf(mx1, __shfl_xor_sync(0xffffffffu, mx1, o));
        }
        float mn0 = fmaxf(m0v, mx0), mn1 = fmaxf(m1v, mx1);
        float sc0 = __expf(m0v - mn0), sc1 = __expf(m1v - mn1);
        m0v = mn0; m1v = mn1;
        float s0 = 0.0f, s1 = 0.0f;
        #pragma unroll
        for (int nf = 0; nf < 8; nf++) {
            acc[nf][0] = __expf(acc[nf][0] - mn0);
            acc[nf][1] = __expf(acc[nf][1] - mn0);
            acc[nf][2] = __expf(acc[nf][2] - mn1);
            acc[nf][3] = __expf(acc[nf][3] - mn1);
            s0 += acc[nf][0] + acc[nf][1];
            s1 += acc[nf][2] + acc[nf][3];
        }
        #pragma unroll
        for (int o = 1; o <= 2; o <<= 1) {
            s0 += __shfl_xor_sync(0xffffffffu, s0, o);
            s1 += __shfl_xor_sync(0xffffffffu, s1, o);
        }
        l0v = l0v * sc0 + s0;
        l1v = l1v * sc1 + s1;
        #pragma unroll
        for (int nf = 0; nf < 8; nf++) {
            Oa[nf][0] *= sc0; Oa[nf][1] *= sc0;
            Oa[nf][2] *= sc1; Oa[nf][3] *= sc1;
        }

        // P -> smem fp16 (warp-own rows), PV via a-ldsm + trans-ldsm V
        #pragma unroll
        for (int nf = 0; nf < 8; nf++) {
            *(__half2*)&Ps[qrow*QST     + nf*8 + 2*c0] =
                __floats2half2_rn(acc[nf][0], acc[nf][1]);
            *(__half2*)&Ps[(qrow+8)*QST + nf*8 + 2*c0] =
                __floats2half2_rn(acc[nf][2], acc[nf][3]);
        }
        __syncwarp();
        #pragma unroll
        for (int kc = 0; kc < 4; kc++) {
            unsigned a4[4];
            ldsm4(a4[0], a4[1], a4[2], a4[3],
                  smaddr(&Ps[(w*16 + goff)*QST + kc*16 + khq]));
            #pragma unroll
            for (int dt = 0; dt < 4; dt++) {
                unsigned vb[4];
                ldsm4t(vb[0], vb[1], vb[2], vb[3],
                       smaddr(&Vs[(kc*16 + goff)*VST + dt*16 + khq]));
                mma16h(Oa[2*dt],   a4, vb[0], vb[1]);
                mma16h(Oa[2*dt+1], a4, vb[2], vb[3]);
            }
        }
        __syncwarp();
    }

    // epilogue: O /= l, write fp16 to g_o1h
    float inv0 = 1.0f / l0v, inv1 = 1.0f / l1v;
    int b = bh >> 4, h = bh & 15;
    __half* O0 = g_o1h + ((size_t)b*NN + q0 + qrow)*DMODEL + h*DK;
    __half* O1 = O0 + 8*DMODEL;
    #pragma unroll
    for (int nf = 0; nf < 8; nf++) {
        *(__half2*)(O0 + nf*8 + 2*c0) = __floats2half2_rn(Oa[nf][0]*inv0, Oa[nf][1]*inv0);
        *(__half2*)(O1 + nf*8 + 2*c0) = __floats2half2_rn(Oa[nf][2]*inv1, Oa[nf][3]*inv1);
    }
}

// ============================================================
extern "C" void kernel_launch(void* const* d_in, const int* in_sizes, int n_in,
                              void* d_out, int out_size) {
    const float* queries = (const float*)d_in[0];
    const float* keys    = (const float*)d_in[1];
    const float* values  = (const float*)d_in[2];
    const float* boxes   = (const float*)d_in[3];
    const float* Wq = (const float*)d_in[4];
    const float* bq = (const float*)d_in[5];
    const float* Wk = (const float*)d_in[6];
    const float* bk = (const float*)d_in[7];
    const float* Wv = (const float*)d_in[8];
    const float* bv = (const float*)d_in[9];
    const float* Wo = (const float*)d_in[10];
    const float* bo = (const float*)d_in[11];
    const float* Wg = (const float*)d_in[12];
    const float* bg = (const float*)d_in[13];
    float* out = (float*)d_out;

    cudaFuncSetAttribute(gemm_tc<0>, cudaFuncAttributeMaxDynamicSharedMemorySize, HSMEM);
    cudaFuncSetAttribute(gemm_tc<1>, cudaFuncAttributeMaxDynamicSharedMemorySize, HSMEM);
    cudaFuncSetAttribute(fused_attn, cudaFuncAttributeMaxDynamicSharedMemorySize,
                         FUSED_SMEM);

    boxfeat_kernel<<<16, 256>>>(boxes);
    prep_kernel<<<dim3(4096, 7), 256>>>(queries, keys, values, Wq, Wk, Wv, Wo);
    geom_kernel<<<dim3(32, 32, 8), 256>>>(Wg, bg);
    gemm_tc<0><<<dim3(8, 32, 3), 256, HSMEM>>>(bq, bk, bv, nullptr);
    fused_attn<<<dim3(4, 128), 256, FUSED_SMEM>>>();
    gemm_tc<1><<<dim3(8, 32, 1), 256, HSMEM>>>(bo, nullptr, nullptr, out);
}

// round 15
// speedup vs baseline: 1.7134x; 1.2658x over previous
#include <cuda_runtime.h>
#include <cuda_fp16.h>
#include <math.h>

#define BB 8
#define NN 512
#define DMODEL 1024
#define HH 16
#define DK 64

// ---- static scratch ----
__device__ __half g_qh[BB*HH*NN*DK];      // fp16, pre-scaled by 1/8
__device__ __half g_kh[BB*HH*NN*DK];
__device__ __half g_vh[BB*HH*NN*DK];
__device__ float g_s[BB*HH*NN*NN];        // geometry bias (log g), fp32
__device__ __half g_o1h[BB*NN*DMODEL];    // attn output, fp16 (feeds O-proj)
__device__ float g_boxf[BB*NN*6];
__device__ __half g_acth[3*BB*NN*DMODEL]; // fp16 activations (q,k,v inputs)
__device__ __half g_wh[4*DMODEL*DMODEL];  // fp16 weights Wq,Wk,Wv,Wo

// ---- helpers ----
__device__ __forceinline__ void mma16h(float* c, const unsigned* a,
                                       unsigned b0, unsigned b1) {
    asm volatile("mma.sync.aligned.m16n8k16.row.col.f32.f16.f16.f32 "
        "{%0,%1,%2,%3},{%4,%5,%6,%7},{%8,%9},{%0,%1,%2,%3};"
        : "+f"(c[0]), "+f"(c[1]), "+f"(c[2]), "+f"(c[3])
        : "r"(a[0]), "r"(a[1]), "r"(a[2]), "r"(a[3]), "r"(b0), "r"(b1));
}
__device__ __forceinline__ void ldsm4(unsigned& r0, unsigned& r1, unsigned& r2v,
                                      unsigned& r3, unsigned a) {
    asm volatile("ldmatrix.sync.aligned.m8n8.x4.shared.b16 {%0,%1,%2,%3}, [%4];"
        : "=r"(r0), "=r"(r1), "=r"(r2v), "=r"(r3) : "r"(a));
}
__device__ __forceinline__ void ldsm4t(unsigned& r0, unsigned& r1, unsigned& r2v,
                                       unsigned& r3, unsigned a) {
    asm volatile("ldmatrix.sync.aligned.m8n8.x4.trans.shared.b16 {%0,%1,%2,%3}, [%4];"
        : "=r"(r0), "=r"(r1), "=r"(r2v), "=r"(r3) : "r"(a));
}
__device__ __forceinline__ void cpa16(unsigned dst, const void* src) {
    asm volatile("cp.async.cg.shared.global [%0], [%1], 16;" :: "r"(dst), "l"(src));
}
__device__ __forceinline__ void cp_commit() {
    asm volatile("cp.async.commit_group;" ::: "memory");
}
__device__ __forceinline__ void cp_wait1() {
    asm volatile("cp.async.wait_group 1;" ::: "memory");
}
__device__ __forceinline__ void cp_wait0() {
    asm volatile("cp.async.wait_group 0;" ::: "memory");
}
__device__ __forceinline__ unsigned smaddr(const void* p) {
    return (unsigned)__cvta_generic_to_shared(p);
}

// ============================================================
// box features
// ============================================================
__global__ void boxfeat_kernel(const float* __restrict__ boxes) {
    int i = blockIdx.x * blockDim.x + threadIdx.x;
    if (i >= BB*NN) return;
    float4 bx = ((const float4*)boxes)[i];
    float cx = 0.5f * (bx.x + bx.z);
    float cy = 0.5f * (bx.y + bx.w);
    float w  = bx.z - bx.x + 1.0f;
    float h  = bx.w - bx.y + 1.0f;
    float* o = &g_boxf[i*6];
    o[0] = cx; o[1] = cy;
    o[2] = 1.0f / w; o[3] = 1.0f / h;
    o[4] = __logf(w); o[5] = __logf(h);
}

// ============================================================
// convert activations + weights to fp16
// ============================================================
__global__ void prep_kernel(const float* __restrict__ q, const float* __restrict__ k,
                            const float* __restrict__ v, const float* __restrict__ wq,
                            const float* __restrict__ wk, const float* __restrict__ wv,
                            const float* __restrict__ wo) {
    int z = blockIdx.y;
    const float* src = (z==0)?q:(z==1)?k:(z==2)?v:(z==3)?wq:(z==4)?wk:(z==5)?wv:wo;
    __half* dst = (z < 3) ? g_acth + (size_t)z*(BB*NN*DMODEL)
                          : g_wh + (size_t)(z-3)*(DMODEL*DMODEL);
    int n4 = (z < 3) ? (BB*NN*DMODEL/4) : (DMODEL*DMODEL/4);
    int i = blockIdx.x*256 + threadIdx.x;
    if (i < n4) {
        float4 a = ((const float4*)src)[i];
        ((__half2*)dst)[2*i]   = __floats2half2_rn(a.x, a.y);
        ((__half2*)dst)[2*i+1] = __floats2half2_rn(a.z, a.w);
    }
}

// ============================================================
// geometry bias via tensor cores:
// per block: 256 (q,k) pairs; emb[256x64] fp16 -> mma vs Wg[16x64] ->
// log(relu(.)+clip) -> g_s for all 16 heads.
// ============================================================
#define EST 72

__global__ void __launch_bounds__(256, 2) geom_kernel(const float* __restrict__ Wg,
                                                      const float* __restrict__ bg) {
    __shared__ __half Es[256][EST];
    __shared__ __half Wgh[16][EST];
    __shared__ float qf[16][6];
    __shared__ float kf[16][6];
    __shared__ float bgs[16];
    int tid = threadIdx.x;
    int b  = blockIdx.z;
    int q0 = blockIdx.y * 16, k0 = blockIdx.x * 16;

    // Wg -> fp16 smem ([16][64], k-contiguous = B operand layout)
    {
        int i = tid * 4;     // 256 threads x 4 floats = 1024
        float4 wv = *(const float4*)(Wg + i);
        int h = i >> 6, d = i & 63;
        Wgh[h][d+0] = __float2half(wv.x);
        Wgh[h][d+1] = __float2half(wv.y);
        Wgh[h][d+2] = __float2half(wv.z);
        Wgh[h][d+3] = __float2half(wv.w);
    }
    if (tid < 16) {
        bgs[tid] = bg[tid];
        #pragma unroll
        for (int j = 0; j < 6; j++) qf[tid][j] = g_boxf[(b*NN + q0 + tid)*6 + j];
    } else if (tid < 32) {
        int t = tid - 16;
        #pragma unroll
        for (int j = 0; j < 6; j++) kf[t][j] = g_boxf[(b*NN + k0 + t)*6 + j];
    }
    __syncthreads();

    // per-pair positional features
    int ty = tid >> 4, tx = tid & 15;
    float pos[4];
    pos[0] = __logf(fmaxf(fabsf(qf[ty][0] - kf[tx][0]) * qf[ty][2], 1e-3f));
    pos[1] = __logf(fmaxf(fabsf(qf[ty][1] - kf[tx][1]) * qf[ty][3], 1e-3f));
    pos[2] = qf[ty][4] - kf[tx][4];
    pos[3] = qf[ty][5] - kf[tx][5];

    const float dm[8] = {1.0f, 0.42169650f, 0.17782794f, 0.07498942f,
                         0.03162278f, 0.01333521f, 0.00562341f, 0.00237137f};
    float sv[32], cvv[32];
    #pragma unroll
    for (int c = 0; c < 4; c++) {
        float p100 = 100.0f * pos[c];
        #pragma unroll
        for (int f = 0; f < 8; f++)
            __sincosf(p100 * dm[f], &sv[c*8+f], &cvv[c*8+f]);
    }
    // emb row: [sin(0..31) | cos(0..31)]
    __half2* er = (__half2*)&Es[tid][0];
    #pragma unroll
    for (int d2 = 0; d2 < 16; d2++)
        er[d2] = __floats2half2_rn(sv[2*d2], sv[2*d2+1]);
    #pragma unroll
    for (int d2 = 0; d2 < 16; d2++)
        er[16+d2] = __floats2half2_rn(cvv[2*d2], cvv[2*d2+1]);
    __syncthreads();

    // mma: warp w handles pairs [w*32, w*32+32) x all 16 heads
    int w = tid >> 5, l = tid & 31;
    int lj   = l & 7;
    int goff = ((l >> 3) & 1) * 8 + lj;
    int khq  = (l >> 4) * 8;

    float acc[2][2][4];
    #pragma unroll
    for (int i = 0; i < 2; i++)
        #pragma unroll
        for (int j = 0; j < 2; j++)
            #pragma unroll
            for (int k = 0; k < 4; k++) acc[i][j][k] = 0.0f;

    #pragma unroll
    for (int kc = 0; kc < 4; kc++) {
        unsigned a[2][4];
        #pragma unroll
        for (int mf = 0; mf < 2; mf++)
            ldsm4(a[mf][0], a[mf][1], a[mf][2], a[mf][3],
                  smaddr(&Es[w*32 + mf*16 + goff][kc*16 + khq]));
        unsigned bb[4];
        ldsm4(bb[0], bb[1], bb[2], bb[3],
              smaddr(&Wgh[goff][kc*16 + khq]));
        #pragma unroll
        for (int mf = 0; mf < 2; mf++) {
            mma16h(acc[mf][0], a[mf], bb[0], bb[2]);
            mma16h(acc[mf][1], a[mf], bb[1], bb[3]);
        }
    }

    // epilogue: + bg, relu, log, scatter to g_s
    #pragma unroll
    for (int mf = 0; mf < 2; mf++) {
        #pragma unroll
        for (int n8 = 0; n8 < 2; n8++) {
            #pragma unroll
            for (int rr = 0; rr < 2; rr++) {
                int p = w*32 + mf*16 + rr*8 + (l >> 2);
                int q = q0 + (p >> 4), k = k0 + (p & 15);
                #pragma unroll
                for (int jj = 0; jj < 2; jj++) {
                    int h = n8*8 + 2*(l & 3) + jj;
                    float v = acc[mf][n8][rr*2 + jj] + bgs[h];
                    g_s[(((size_t)b*HH + h)*NN + q)*NN + k] =
                        __logf(fmaxf(v, 1e-6f));
                }
            }
        }
    }
}

// ============================================================
// fp16 GEMM, 128x128 CTA tile, 8 warps of 32x64, KTILE=64 halves,
// 3-stage cp.async, ldmatrix b16, mma m16n8k16.
// MODE 0: QKV (A=g_acth[z], B=g_wh[z], fp16 scatter, z==0 scaled 1/8)
// MODE 1: O-proj (A=g_o1h, B=g_wh[3], dst=Cout, fp32)
// ============================================================
#define HST 72
#define HTILE (128*HST)
#define HSMEM (3 * 2 * HTILE * 2)           // 110592 B

template<int MODE>
__global__ void __launch_bounds__(256, 2) gemm_tc(
    const float* __restrict__ b0p, const float* __restrict__ b1p,
    const float* __restrict__ b2p, float* __restrict__ Cout)
{
    constexpr int KD  = DMODEL;
    constexpr int NIT = KD / 64;
    extern __shared__ __half hsm[];

    int t = threadIdx.x;
    int m0 = blockIdx.y * 128, n0 = blockIdx.x * 128;
    int z = blockIdx.z;

    const __half *A, *B;
    const float *bias;
    if (MODE == 0) {
        A = g_acth + (size_t)z*(BB*NN*DMODEL);
        B = g_wh   + (size_t)z*(DMODEL*DMODEL);
        bias = (z == 0) ? b0p : (z == 1) ? b1p : b2p;
    } else {
        A = g_o1h;
        B = g_wh + 3*(size_t)(DMODEL*DMODEL);
        bias = b0p;
    }

    int lrows[4], lhc[4];
    #pragma unroll
    for (int i = 0; i < 4; i++) {
        int idx = t + i*256;
        lrows[i] = idx >> 3;
        lhc[i]   = (idx & 7) * 8;
    }
    unsigned sbase = smaddr(hsm);

    int w = t >> 5, l = t & 31;
    int wm = w & 3, wn = w >> 2;
    int lj   = l & 7;
    int goff = ((l >> 3) & 1) * 8 + lj;
    int khq  = (l >> 4) * 8;

    float acc[2][8][4];
    #pragma unroll
    for (int i = 0; i < 2; i++)
        #pragma unroll
        for (int j = 0; j < 8; j++)
            #pragma unroll
            for (int k = 0; k < 4; k++) acc[i][j][k] = 0.0f;

    #pragma unroll
    for (int p = 0; p < 2; p++) {
        unsigned ab = sbase + (unsigned)(p*2*HTILE)*2u;
        #pragma unroll
        for (int i = 0; i < 4; i++) {
            cpa16(ab + (lrows[i]*HST + lhc[i])*2u,
                  A + (size_t)(m0 + lrows[i])*KD + p*64 + lhc[i]);
            cpa16(ab + (HTILE + lrows[i]*HST + lhc[i])*2u,
                  B + (size_t)(n0 + lrows[i])*KD + p*64 + lhc[i]);
        }
        cp_commit();
    }

    for (int j = 0; j < NIT; j++) {
        cp_wait1();
        __syncthreads();
        if (j + 2 < NIT) {
            int s = (j + 2) % 3;
            unsigned ab = sbase + (unsigned)(s*2*HTILE)*2u;
            int kb = (j + 2) * 64;
            #pragma unroll
            for (int i = 0; i < 4; i++) {
                cpa16(ab + (lrows[i]*HST + lhc[i])*2u,
                      A + (size_t)(m0 + lrows[i])*KD + kb + lhc[i]);
                cpa16(ab + (HTILE + lrows[i]*HST + lhc[i])*2u,
                      B + (size_t)(n0 + lrows[i])*KD + kb + lhc[i]);
            }
        }
        cp_commit();

        int s = j % 3;
        const __half* As = hsm + s*2*HTILE;
        const __half* Bs = As + HTILE;
        #pragma unroll
        for (int kc = 0; kc < 4; kc++) {
            unsigned a[2][4];
            #pragma unroll
            for (int mf = 0; mf < 2; mf++)
                ldsm4(a[mf][0], a[mf][1], a[mf][2], a[mf][3],
                      smaddr(&As[(wm*32 + mf*16 + goff)*HST + kc*16 + khq]));
            #pragma unroll
            for (int nt = 0; nt < 4; nt++) {
                unsigned bb[4];
                ldsm4(bb[0], bb[1], bb[2], bb[3],
                      smaddr(&Bs[(wn*64 + nt*16 + goff)*HST + kc*16 + khq]));
                #pragma unroll
                for (int mf = 0; mf < 2; mf++) {
                    mma16h(acc[mf][2*nt],   a[mf], bb[0], bb[2]);
                    mma16h(acc[mf][2*nt+1], a[mf], bb[1], bb[3]);
                }
            }
        }
    }

    float qsc = (MODE == 0 && z == 0) ? 0.125f : 1.0f;
    #pragma unroll
    for (int mf = 0; mf < 2; mf++) {
        #pragma unroll
        for (int nf = 0; nf < 8; nf++) {
            int col = n0 + wn*64 + nf*8 + 2*(l & 3);
            float2 b2 = *(const float2*)(bias + col);
            #pragma unroll
            for (int rr = 0; rr < 2; rr++) {
                int row = m0 + wm*32 + mf*16 + rr*8 + (l >> 2);
                float v0 = acc[mf][nf][rr*2 + 0] + b2.x;
                float v1 = acc[mf][nf][rr*2 + 1] + b2.y;
                if (MODE == 0) {
                    int h = col >> 6, d = col & 63;
                    int bq = row >> 9, ntok = row & (NN-1);
                    __half* dstp = (z == 0) ? g_qh : (z == 1) ? g_kh : g_vh;
                    *(__half2*)&dstp[(((size_t)bq*HH + h)*NN + ntok)*DK + d] =
                        __floats2half2_rn(v0*qsc, v1*qsc);
                } else {
                    *(float2*)&Cout[(size_t)row*DMODEL + col] = make_float2(v0, v1);
                }
            }
        }
    }
}

// ============================================================
// fused attention, fp16 MMAs: S = bias + Q'Kt (Q' pre-scaled),
// online softmax, O += P V.  CTA: 128 q x one bh, 8 warps of 16 q.
// ============================================================
#define QST 72
#define KST 72
#define VST 72
#define FUSED_SMEM ((2*64*KST + 2*64*VST + 128*QST) * 2)

__global__ void __launch_bounds__(256, 2) fused_attn() {
    extern __shared__ __half smh[];
    __half* KsB = smh;
    __half* VsB = smh + 2*64*KST;
    __half* Ps  = VsB + 2*64*VST;

    int t = threadIdx.x;
    int bh = blockIdx.y;
    int q0 = blockIdx.x * 128;
    const __half* Qg = g_qh + ((size_t)bh*NN + q0)*DK;
    const __half* Kg = g_kh + (size_t)bh*NN*DK;
    const __half* Vg = g_vh + (size_t)bh*NN*DK;
    const float*  Sg = g_s  + (size_t)bh*NN*NN;

    int w = t >> 5, l = t & 31;
    int r0 = l >> 2, c0 = l & 3;
    int qrow = w*16 + r0;
    int lj   = l & 7;
    int goff = ((l >> 3) & 1) * 8 + lj;
    int khq  = (l >> 4) * 8;

    #pragma unroll
    for (int i = 0; i < 4; i++) {
        int idx = t + i*256;
        int row = idx >> 3, col = (idx & 7) * 8;
        cpa16(smaddr(Ps + row*QST + col), Qg + row*DK + col);
    }
    #pragma unroll
    for (int i = 0; i < 2; i++) {
        int idx = t + i*256;
        int row = idx >> 3, col = (idx & 7) * 8;
        cpa16(smaddr(KsB + row*KST + col), Kg + row*DK + col);
        cpa16(smaddr(VsB + row*VST + col), Vg + row*DK + col);
    }
    cp_commit();
    cp_wait0();
    __syncthreads();

    unsigned qa[4][4];
    #pragma unroll
    for (int kc = 0; kc < 4; kc++)
        ldsm4(qa[kc][0], qa[kc][1], qa[kc][2], qa[kc][3],
              smaddr(&Ps[(w*16 + goff)*QST + kc*16 + khq]));
    __syncthreads();

    float Oa[8][4];
    #pragma unroll
    for (int nf = 0; nf < 8; nf++)
        #pragma unroll
        for (int k = 0; k < 4; k++) Oa[nf][k] = 0.0f;
    float m0v = -INFINITY, m1v = -INFINITY, l0v = 0.0f, l1v = 0.0f;

    const int NT = NN / 64;
    for (int j = 0; j < NT; j++) {
        if (j > 0) {
            cp_wait0();
            __syncthreads();
        }
        if (j + 1 < NT) {
            int nb = (j + 1) & 1;
            __half* Ksn = KsB + nb*64*KST;
            __half* Vsn = VsB + nb*64*VST;
            #pragma unroll
            for (int i = 0; i < 2; i++) {
                int idx = t + i*256;
                int row = idx >> 3, col = (idx & 7) * 8;
                cpa16(smaddr(Ksn + row*KST + col), Kg + ((j+1)*64 + row)*DK + col);
                cpa16(smaddr(Vsn + row*VST + col), Vg + ((j+1)*64 + row)*DK + col);
            }
        }
        cp_commit();

        const __half* Ks = KsB + (j & 1)*64*KST;
        const __half* Vs = VsB + (j & 1)*64*VST;

        float acc[8][4];
        {
            const float* br0 = Sg + (size_t)(q0 + qrow)*NN + j*64;
            const float* br1 = br0 + 8*NN;
            #pragma unroll
            for (int nf = 0; nf < 8; nf++) {
                float2 t0 = *(const float2*)(br0 + nf*8 + 2*c0);
                float2 t1 = *(const float2*)(br1 + nf*8 + 2*c0);
                acc[nf][0] = t0.x; acc[nf][1] = t0.y;
                acc[nf][2] = t1.x; acc[nf][3] = t1.y;
            }
        }
        #pragma unroll
        for (int kc = 0; kc < 4; kc++) {
            #pragma unroll
            for (int nt = 0; nt < 4; nt++) {
                unsigned bb[4];
                ldsm4(bb[0], bb[1], bb[2], bb[3],
                      smaddr(&Ks[(nt*16 + goff)*KST + kc*16 + khq]));
                mma16h(acc[2*nt],   qa[kc], bb[0], bb[2]);
                mma16h(acc[2*nt+1], qa[kc], bb[1], bb[3]);
            }
        }

        float mx0 = -INFINITY, mx1 = -INFINITY;
        #pragma unroll
        for (int nf = 0; nf < 8; nf++) {
            mx0 = fmaxf(mx0, fmaxf(acc[nf][0], acc[nf][1]));
            mx1 = fmaxf(mx1, fmaxf(acc[nf][2], acc[nf][3]));
        }
        #pragma unroll
        for (int o = 1; o <= 2; o <<= 1) {
            mx0 = fmaxf(mx0, __shfl_xor_sync(0xffffffffu, mx0, o));
            mx1 = fmaxf(mx1, __shfl_xor_sync(0xffffffffu, mx1, o));
        }
        float mn0 = fmaxf(m0v, mx0), mn1 = fmaxf(m1v, mx1);
        float sc0 = __expf(m0v - mn0), sc1 = __expf(m1v - mn1);
        m0v = mn0; m1v = mn1;
        float s0 = 0.0f, s1 = 0.0f;
        #pragma unroll
        for (int nf = 0; nf < 8; nf++) {
            acc[nf][0] = __expf(acc[nf][0] - mn0);
            acc[nf][1] = __expf(acc[nf][1] - mn0);
            acc[nf][2] = __expf(acc[nf][2] - mn1);
            acc[nf][3] = __expf(acc[nf][3] - mn1);
            s0 += acc[nf][0] + acc[nf][1];
            s1 += acc[nf][2] + acc[nf][3];
        }
        #pragma unroll
        for (int o = 1; o <= 2; o <<= 1) {
            s0 += __shfl_xor_sync(0xffffffffu, s0, o);
            s1 += __shfl_xor_sync(0xffffffffu, s1, o);
        }
        l0v = l0v * sc0 + s0;
        l1v = l1v * sc1 + s1;
        #pragma unroll
        for (int nf = 0; nf < 8; nf++) {
            Oa[nf][0] *= sc0; Oa[nf][1] *= sc0;
            Oa[nf][2] *= sc1; Oa[nf][3] *= sc1;
        }

        #pragma unroll
        for (int nf = 0; nf < 8; nf++) {
            *(__half2*)&Ps[qrow*QST     + nf*8 + 2*c0] =
                __floats2half2_rn(acc[nf][0], acc[nf][1]);
            *(__half2*)&Ps[(qrow+8)*QST + nf*8 + 2*c0] =
                __floats2half2_rn(acc[nf][2], acc[nf][3]);
        }
        __syncwarp();
        #pragma unroll
        for (int kc = 0; kc < 4; kc++) {
            unsigned a4[4];
            ldsm4(a4[0], a4[1], a4[2], a4[3],
                  smaddr(&Ps[(w*16 + goff)*QST + kc*16 + khq]));
            #pragma unroll
            for (int dt = 0; dt < 4; dt++) {
                unsigned vb[4];
                ldsm4t(vb[0], vb[1], vb[2], vb[3],
                       smaddr(&Vs[(kc*16 + goff)*VST + dt*16 + khq]));
                mma16h(Oa[2*dt],   a4, vb[0], vb[1]);
                mma16h(Oa[2*dt+1], a4, vb[2], vb[3]);
            }
        }
        __syncwarp();
    }

    float inv0 = 1.0f / l0v, inv1 = 1.0f / l1v;
    int b = bh >> 4, h = bh & 15;
    __half* O0 = g_o1h + ((size_t)b*NN + q0 + qrow)*DMODEL + h*DK;
    __half* O1 = O0 + 8*DMODEL;
    #pragma unroll
    for (int nf = 0; nf < 8; nf++) {
        *(__half2*)(O0 + nf*8 + 2*c0) = __floats2half2_rn(Oa[nf][0]*inv0, Oa[nf][1]*inv0);
        *(__half2*)(O1 + nf*8 + 2*c0) = __floats2half2_rn(Oa[nf][2]*inv1, Oa[nf][3]*inv1);
    }
}

// ============================================================
extern "C" void kernel_launch(void* const* d_in, const int* in_sizes, int n_in,
                              void* d_out, int out_size) {
    const float* queries = (const float*)d_in[0];
    const float* keys    = (const float*)d_in[1];
    const float* values  = (const float*)d_in[2];
    const float* boxes   = (const float*)d_in[3];
    const float* Wq = (const float*)d_in[4];
    const float* bq = (const float*)d_in[5];
    const float* Wk = (const float*)d_in[6];
    const float* bk = (const float*)d_in[7];
    const float* Wv = (const float*)d_in[8];
    const float* bv = (const float*)d_in[9];
    const float* Wo = (const float*)d_in[10];
    const float* bo = (const float*)d_in[11];
    const float* Wg = (const float*)d_in[12];
    const float* bg = (const float*)d_in[13];
    float* out = (float*)d_out;

    cudaFuncSetAttribute(gemm_tc<0>, cudaFuncAttributeMaxDynamicSharedMemorySize, HSMEM);
    cudaFuncSetAttribute(gemm_tc<1>, cudaFuncAttributeMaxDynamicSharedMemorySize, HSMEM);
    cudaFuncSetAttribute(fused_attn, cudaFuncAttributeMaxDynamicSharedMemorySize,
                         FUSED_SMEM);

    boxfeat_kernel<<<16, 256>>>(boxes);
    prep_kernel<<<dim3(4096, 7), 256>>>(queries, keys, values, Wq, Wk, Wv, Wo);
    geom_kernel<<<dim3(32, 32, 8), 256>>>(Wg, bg);
    gemm_tc<0><<<dim3(8, 32, 3), 256, HSMEM>>>(bq, bk, bv, nullptr);
    fused_attn<<<dim3(4, 128), 256, FUSED_SMEM>>>();
    gemm_tc<1><<<dim3(8, 32, 1), 256, HSMEM>>>(bo, nullptr, nullptr, out);
}

// round 16
// speedup vs baseline: 1.7321x; 1.0109x over previous
#include <cuda_runtime.h>
#include <cuda_fp16.h>
#include <math.h>

#define BB 8
#define NN 512
#define DMODEL 1024
#define HH 16
#define DK 64

// ---- static scratch ----
__device__ __half g_qh[BB*HH*NN*DK];      // fp16, pre-scaled by 1/8
__device__ __half g_kh[BB*HH*NN*DK];
__device__ __half g_vh[BB*HH*NN*DK];
__device__ float g_s[BB*HH*NN*NN];        // geometry bias (log g), fp32
__device__ __half g_o1h[BB*NN*DMODEL];    // attn output, fp16 (feeds O-proj)
__device__ float g_boxf[BB*NN*6];
__device__ __half g_acth[3*BB*NN*DMODEL]; // fp16 activations (q,k,v inputs)
__device__ __half g_wh[4*DMODEL*DMODEL];  // fp16 weights Wq,Wk,Wv,Wo

// ---- side stream + events, created at static-init time (host objects only;
// no device memory) so no CUDA API churn happens inside graph capture ----
static cudaStream_t g_s2;
static cudaEvent_t g_evFork, g_evJoin;
static struct StreamInit {
    StreamInit() {
        cudaStreamCreateWithFlags(&g_s2, cudaStreamNonBlocking);
        cudaEventCreateWithFlags(&g_evFork, cudaEventDisableTiming);
        cudaEventCreateWithFlags(&g_evJoin, cudaEventDisableTiming);
    }
} g_streamInit;

// ---- helpers ----
__device__ __forceinline__ void mma16h(float* c, const unsigned* a,
                                       unsigned b0, unsigned b1) {
    asm volatile("mma.sync.aligned.m16n8k16.row.col.f32.f16.f16.f32 "
        "{%0,%1,%2,%3},{%4,%5,%6,%7},{%8,%9},{%0,%1,%2,%3};"
        : "+f"(c[0]), "+f"(c[1]), "+f"(c[2]), "+f"(c[3])
        : "r"(a[0]), "r"(a[1]), "r"(a[2]), "r"(a[3]), "r"(b0), "r"(b1));
}
__device__ __forceinline__ void ldsm4(unsigned& r0, unsigned& r1, unsigned& r2v,
                                      unsigned& r3, unsigned a) {
    asm volatile("ldmatrix.sync.aligned.m8n8.x4.shared.b16 {%0,%1,%2,%3}, [%4];"
        : "=r"(r0), "=r"(r1), "=r"(r2v), "=r"(r3) : "r"(a));
}
__device__ __forceinline__ void ldsm4t(unsigned& r0, unsigned& r1, unsigned& r2v,
                                       unsigned& r3, unsigned a) {
    asm volatile("ldmatrix.sync.aligned.m8n8.x4.trans.shared.b16 {%0,%1,%2,%3}, [%4];"
        : "=r"(r0), "=r"(r1), "=r"(r2v), "=r"(r3) : "r"(a));
}
__device__ __forceinline__ void cpa16(unsigned dst, const void* src) {
    asm volatile("cp.async.cg.shared.global [%0], [%1], 16;" :: "r"(dst), "l"(src));
}
__device__ __forceinline__ void cp_commit() {
    asm volatile("cp.async.commit_group;" ::: "memory");
}
__device__ __forceinline__ void cp_wait1() {
    asm volatile("cp.async.wait_group 1;" ::: "memory");
}
__device__ __forceinline__ void cp_wait0() {
    asm volatile("cp.async.wait_group 0;" ::: "memory");
}
__device__ __forceinline__ unsigned smaddr(const void* p) {
    return (unsigned)__cvta_generic_to_shared(p);
}

// ============================================================
// box features
// ============================================================
__global__ void boxfeat_kernel(const float* __restrict__ boxes) {
    int i = blockIdx.x * blockDim.x + threadIdx.x;
    if (i >= BB*NN) return;
    float4 bx = ((const float4*)boxes)[i];
    float cx = 0.5f * (bx.x + bx.z);
    float cy = 0.5f * (bx.y + bx.w);
    float w  = bx.z - bx.x + 1.0f;
    float h  = bx.w - bx.y + 1.0f;
    float* o = &g_boxf[i*6];
    o[0] = cx; o[1] = cy;
    o[2] = 1.0f / w; o[3] = 1.0f / h;
    o[4] = __logf(w); o[5] = __logf(h);
}

// ============================================================
// convert activations + weights to fp16
// ============================================================
__global__ void prep_kernel(const float* __restrict__ q, const float* __restrict__ k,
                            const float* __restrict__ v, const float* __restrict__ wq,
                            const float* __restrict__ wk, const float* __restrict__ wv,
                            const float* __restrict__ wo) {
    int z = blockIdx.y;
    const float* src = (z==0)?q:(z==1)?k:(z==2)?v:(z==3)?wq:(z==4)?wk:(z==5)?wv:wo;
    __half* dst = (z < 3) ? g_acth + (size_t)z*(BB*NN*DMODEL)
                          : g_wh + (size_t)(z-3)*(DMODEL*DMODEL);
    int n4 = (z < 3) ? (BB*NN*DMODEL/4) : (DMODEL*DMODEL/4);
    int i = blockIdx.x*256 + threadIdx.x;
    if (i < n4) {
        float4 a = ((const float4*)src)[i];
        ((__half2*)dst)[2*i]   = __floats2half2_rn(a.x, a.y);
        ((__half2*)dst)[2*i+1] = __floats2half2_rn(a.z, a.w);
    }
}

// ============================================================
// geometry bias via tensor cores
// ============================================================
#define EST 72

__global__ void __launch_bounds__(256, 2) geom_kernel(const float* __restrict__ Wg,
                                                      const float* __restrict__ bg) {
    __shared__ __half Es[256][EST];
    __shared__ __half Wgh[16][EST];
    __shared__ float qf[16][6];
    __shared__ float kf[16][6];
    __shared__ float bgs[16];
    int tid = threadIdx.x;
    int b  = blockIdx.z;
    int q0 = blockIdx.y * 16, k0 = blockIdx.x * 16;

    {
        int i = tid * 4;
        float4 wv = *(const float4*)(Wg + i);
        int h = i >> 6, d = i & 63;
        Wgh[h][d+0] = __float2half(wv.x);
        Wgh[h][d+1] = __float2half(wv.y);
        Wgh[h][d+2] = __float2half(wv.z);
        Wgh[h][d+3] = __float2half(wv.w);
    }
    if (tid < 16) {
        bgs[tid] = bg[tid];
        #pragma unroll
        for (int j = 0; j < 6; j++) qf[tid][j] = g_boxf[(b*NN + q0 + tid)*6 + j];
    } else if (tid < 32) {
        int t = tid - 16;
        #pragma unroll
        for (int j = 0; j < 6; j++) kf[t][j] = g_boxf[(b*NN + k0 + t)*6 + j];
    }
    __syncthreads();

    int ty = tid >> 4, tx = tid & 15;
    float pos[4];
    pos[0] = __logf(fmaxf(fabsf(qf[ty][0] - kf[tx][0]) * qf[ty][2], 1e-3f));
    pos[1] = __logf(fmaxf(fabsf(qf[ty][1] - kf[tx][1]) * qf[ty][3], 1e-3f));
    pos[2] = qf[ty][4] - kf[tx][4];
    pos[3] = qf[ty][5] - kf[tx][5];

    const float dm[8] = {1.0f, 0.42169650f, 0.17782794f, 0.07498942f,
                         0.03162278f, 0.01333521f, 0.00562341f, 0.00237137f};
    float sv[32], cvv[32];
    #pragma unroll
    for (int c = 0; c < 4; c++) {
        float p100 = 100.0f * pos[c];
        #pragma unroll
        for (int f = 0; f < 8; f++)
            __sincosf(p100 * dm[f], &sv[c*8+f], &cvv[c*8+f]);
    }
    __half2* er = (__half2*)&Es[tid][0];
    #pragma unroll
    for (int d2 = 0; d2 < 16; d2++)
        er[d2] = __floats2half2_rn(sv[2*d2], sv[2*d2+1]);
    #pragma unroll
    for (int d2 = 0; d2 < 16; d2++)
        er[16+d2] = __floats2half2_rn(cvv[2*d2], cvv[2*d2+1]);
    __syncthreads();

    int w = tid >> 5, l = tid & 31;
    int lj   = l & 7;
    int goff = ((l >> 3) & 1) * 8 + lj;
    int khq  = (l >> 4) * 8;

    float acc[2][2][4];
    #pragma unroll
    for (int i = 0; i < 2; i++)
        #pragma unroll
        for (int j = 0; j < 2; j++)
            #pragma unroll
            for (int k = 0; k < 4; k++) acc[i][j][k] = 0.0f;

    #pragma unroll
    for (int kc = 0; kc < 4; kc++) {
        unsigned a[2][4];
        #pragma unroll
        for (int mf = 0; mf < 2; mf++)
            ldsm4(a[mf][0], a[mf][1], a[mf][2], a[mf][3],
                  smaddr(&Es[w*32 + mf*16 + goff][kc*16 + khq]));
        unsigned bb[4];
        ldsm4(bb[0], bb[1], bb[2], bb[3],
              smaddr(&Wgh[goff][kc*16 + khq]));
        #pragma unroll
        for (int mf = 0; mf < 2; mf++) {
            mma16h(acc[mf][0], a[mf], bb[0], bb[2]);
            mma16h(acc[mf][1], a[mf], bb[1], bb[3]);
        }
    }

    #pragma unroll
    for (int mf = 0; mf < 2; mf++) {
        #pragma unroll
        for (int n8 = 0; n8 < 2; n8++) {
            #pragma unroll
            for (int rr = 0; rr < 2; rr++) {
                int p = w*32 + mf*16 + rr*8 + (l >> 2);
                int q = q0 + (p >> 4), k = k0 + (p & 15);
                #pragma unroll
                for (int jj = 0; jj < 2; jj++) {
                    int h = n8*8 + 2*(l & 3) + jj;
                    float v = acc[mf][n8][rr*2 + jj] + bgs[h];
                    g_s[(((size_t)b*HH + h)*NN + q)*NN + k] =
                        __logf(fmaxf(v, 1e-6f));
                }
            }
        }
    }
}

// ============================================================
// fp16 GEMM, 128x128 CTA tile, 8 warps of 32x64, KTILE=64 halves,
// 3-stage cp.async, ldmatrix b16, mma m16n8k16.
// ============================================================
#define HST 72
#define HTILE (128*HST)
#define HSMEM (3 * 2 * HTILE * 2)

template<int MODE>
__global__ void __launch_bounds__(256, 2) gemm_tc(
    const float* __restrict__ b0p, const float* __restrict__ b1p,
    const float* __restrict__ b2p, float* __restrict__ Cout)
{
    constexpr int KD  = DMODEL;
    constexpr int NIT = KD / 64;
    extern __shared__ __half hsm[];

    int t = threadIdx.x;
    int m0 = blockIdx.y * 128, n0 = blockIdx.x * 128;
    int z = blockIdx.z;

    const __half *A, *B;
    const float *bias;
    if (MODE == 0) {
        A = g_acth + (size_t)z*(BB*NN*DMODEL);
        B = g_wh   + (size_t)z*(DMODEL*DMODEL);
        bias = (z == 0) ? b0p : (z == 1) ? b1p : b2p;
    } else {
        A = g_o1h;
        B = g_wh + 3*(size_t)(DMODEL*DMODEL);
        bias = b0p;
    }

    int lrows[4], lhc[4];
    #pragma unroll
    for (int i = 0; i < 4; i++) {
        int idx = t + i*256;
        lrows[i] = idx >> 3;
        lhc[i]   = (idx & 7) * 8;
    }
    unsigned sbase = smaddr(hsm);

    int w = t >> 5, l = t & 31;
    int wm = w & 3, wn = w >> 2;
    int lj   = l & 7;
    int goff = ((l >> 3) & 1) * 8 + lj;
    int khq  = (l >> 4) * 8;

    float acc[2][8][4];
    #pragma unroll
    for (int i = 0; i < 2; i++)
        #pragma unroll
        for (int j = 0; j < 8; j++)
            #pragma unroll
            for (int k = 0; k < 4; k++) acc[i][j][k] = 0.0f;

    #pragma unroll
    for (int p = 0; p < 2; p++) {
        unsigned ab = sbase + (unsigned)(p*2*HTILE)*2u;
        #pragma unroll
        for (int i = 0; i < 4; i++) {
            cpa16(ab + (lrows[i]*HST + lhc[i])*2u,
                  A + (size_t)(m0 + lrows[i])*KD + p*64 + lhc[i]);
            cpa16(ab + (HTILE + lrows[i]*HST + lhc[i])*2u,
                  B + (size_t)(n0 + lrows[i])*KD + p*64 + lhc[i]);
        }
        cp_commit();
    }

    for (int j = 0; j < NIT; j++) {
        cp_wait1();
        __syncthreads();
        if (j + 2 < NIT) {
            int s = (j + 2) % 3;
            unsigned ab = sbase + (unsigned)(s*2*HTILE)*2u;
            int kb = (j + 2) * 64;
            #pragma unroll
            for (int i = 0; i < 4; i++) {
                cpa16(ab + (lrows[i]*HST + lhc[i])*2u,
                      A + (size_t)(m0 + lrows[i])*KD + kb + lhc[i]);
                cpa16(ab + (HTILE + lrows[i]*HST + lhc[i])*2u,
                      B + (size_t)(n0 + lrows[i])*KD + kb + lhc[i]);
            }
        }
        cp_commit();

        int s = j % 3;
        const __half* As = hsm + s*2*HTILE;
        const __half* Bs = As + HTILE;
        #pragma unroll
        for (int kc = 0; kc < 4; kc++) {
            unsigned a[2][4];
            #pragma unroll
            for (int mf = 0; mf < 2; mf++)
                ldsm4(a[mf][0], a[mf][1], a[mf][2], a[mf][3],
                      smaddr(&As[(wm*32 + mf*16 + goff)*HST + kc*16 + khq]));
            #pragma unroll
            for (int nt = 0; nt < 4; nt++) {
                unsigned bb[4];
                ldsm4(bb[0], bb[1], bb[2], bb[3],
                      smaddr(&Bs[(wn*64 + nt*16 + goff)*HST + kc*16 + khq]));
                #pragma unroll
                for (int mf = 0; mf < 2; mf++) {
                    mma16h(acc[mf][2*nt],   a[mf], bb[0], bb[2]);
                    mma16h(acc[mf][2*nt+1], a[mf], bb[1], bb[3]);
                }
            }
        }
    }

    float qsc = (MODE == 0 && z == 0) ? 0.125f : 1.0f;
    #pragma unroll
    for (int mf = 0; mf < 2; mf++) {
        #pragma unroll
        for (int nf = 0; nf < 8; nf++) {
            int col = n0 + wn*64 + nf*8 + 2*(l & 3);
            float2 b2 = *(const float2*)(bias + col);
            #pragma unroll
            for (int rr = 0; rr < 2; rr++) {
                int row = m0 + wm*32 + mf*16 + rr*8 + (l >> 2);
                float v0 = acc[mf][nf][rr*2 + 0] + b2.x;
                float v1 = acc[mf][nf][rr*2 + 1] + b2.y;
                if (MODE == 0) {
                    int h = col >> 6, d = col & 63;
                    int bq = row >> 9, ntok = row & (NN-1);
                    __half* dstp = (z == 0) ? g_qh : (z == 1) ? g_kh : g_vh;
                    *(__half2*)&dstp[(((size_t)bq*HH + h)*NN + ntok)*DK + d] =
                        __floats2half2_rn(v0*qsc, v1*qsc);
                } else {
                    *(float2*)&Cout[(size_t)row*DMODEL + col] = make_float2(v0, v1);
                }
            }
        }
    }
}

// ============================================================
// fused attention, fp16 MMAs
// ============================================================
#define QST 72
#define KST 72
#define VST 72
#define FUSED_SMEM ((2*64*KST + 2*64*VST + 128*QST) * 2)

__global__ void __launch_bounds__(256, 2) fused_attn() {
    extern __shared__ __half smh[];
    __half* KsB = smh;
    __half* VsB = smh + 2*64*KST;
    __half* Ps  = VsB + 2*64*VST;

    int t = threadIdx.x;
    int bh = blockIdx.y;
    int q0 = blockIdx.x * 128;
    const __half* Qg = g_qh + ((size_t)bh*NN + q0)*DK;
    const __half* Kg = g_kh + (size_t)bh*NN*DK;
    const __half* Vg = g_vh + (size_t)bh*NN*DK;
    const float*  Sg = g_s  + (size_t)bh*NN*NN;

    int w = t >> 5, l = t & 31;
    int r0 = l >> 2, c0 = l & 3;
    int qrow = w*16 + r0;
    int lj   = l & 7;
    int goff = ((l >> 3) & 1) * 8 + lj;
    int khq  = (l >> 4) * 8;

    #pragma unroll
    for (int i = 0; i < 4; i++) {
        int idx = t + i*256;
        int row = idx >> 3, col = (idx & 7) * 8;
        cpa16(smaddr(Ps + row*QST + col), Qg + row*DK + col);
    }
    #pragma unroll
    for (int i = 0; i < 2; i++) {
        int idx = t + i*256;
        int row = idx >> 3, col = (idx & 7) * 8;
        cpa16(smaddr(KsB + row*KST + col), Kg + row*DK + col);
        cpa16(smaddr(VsB + row*VST + col), Vg + row*DK + col);
    }
    cp_commit();
    cp_wait0();
    __syncthreads();

    unsigned qa[4][4];
    #pragma unroll
    for (int kc = 0; kc < 4; kc++)
        ldsm4(qa[kc][0], qa[kc][1], qa[kc][2], qa[kc][3],
              smaddr(&Ps[(w*16 + goff)*QST + kc*16 + khq]));
    __syncthreads();

    float Oa[8][4];
    #pragma unroll
    for (int nf = 0; nf < 8; nf++)
        #pragma unroll
        for (int k = 0; k < 4; k++) Oa[nf][k] = 0.0f;
    float m0v = -INFINITY, m1v = -INFINITY, l0v = 0.0f, l1v = 0.0f;

    const int NT = NN / 64;
    for (int j = 0; j < NT; j++) {
        if (j > 0) {
            cp_wait0();
            __syncthreads();
        }
        if (j + 1 < NT) {
            int nb = (j + 1) & 1;
            __half* Ksn = KsB + nb*64*KST;
            __half* Vsn = VsB + nb*64*VST;
            #pragma unroll
            for (int i = 0; i < 2; i++) {
                int idx = t + i*256;
                int row = idx >> 3, col = (idx & 7) * 8;
                cpa16(smaddr(Ksn + row*KST + col), Kg + ((j+1)*64 + row)*DK + col);
                cpa16(smaddr(Vsn + row*VST + col), Vg + ((j+1)*64 + row)*DK + col);
            }
        }
        cp_commit();

        const __half* Ks = KsB + (j & 1)*64*KST;
        const __half* Vs = VsB + (j & 1)*64*VST;

        float acc[8][4];
        {
            const float* br0 = Sg + (size_t)(q0 + qrow)*NN + j*64;
            const float* br1 = br0 + 8*NN;
            #pragma unroll
            for (int nf = 0; nf < 8; nf++) {
                float2 t0 = *(const float2*)(br0 + nf*8 + 2*c0);
                float2 t1 = *(const float2*)(br1 + nf*8 + 2*c0);
                acc[nf][0] = t0.x; acc[nf][1] = t0.y;
                acc[nf][2] = t1.x; acc[nf][3] = t1.y;
            }
        }
        #pragma unroll
        for (int kc = 0; kc < 4; kc++) {
            #pragma unroll
            for (int nt = 0; nt < 4; nt++) {
                unsigned bb[4];
                ldsm4(bb[0], bb[1], bb[2], bb[3],
                      smaddr(&Ks[(nt*16 + goff)*KST + kc*16 + khq]));
                mma16h(acc[2*nt],   qa[kc], bb[0], bb[2]);
                mma16h(acc[2*nt+1], qa[kc], bb[1], bb[3]);
            }
        }

        float mx0 = -INFINITY, mx1 = -INFINITY;
        #pragma unroll
        for (int nf = 0; nf < 8; nf++) {
            mx0 = fmaxf(mx0, fmaxf(acc[nf][0], acc[nf][1]));
            mx1 = fmaxf(mx1, fmaxf(acc[nf][2], acc[nf][3]));
        }
        #pragma unroll
        for (int o = 1; o <= 2; o <<= 1) {
            mx0 = fmaxf(mx0, __shfl_xor_sync(0xffffffffu, mx0, o));
            mx1 = fmaxf(mx1, __shfl_xor_sync(0xffffffffu, mx1, o));
        }
        float mn0 = fmaxf(m0v, mx0), mn1 = fmaxf(m1v, mx1);
        float sc0 = __expf(m0v - mn0), sc1 = __expf(m1v - mn1);
        m0v = mn0; m1v = mn1;
        float s0 = 0.0f, s1 = 0.0f;
        #pragma unroll
        for (int nf = 0; nf < 8; nf++) {
            acc[nf][0] = __expf(acc[nf][0] - mn0);
            acc[nf][1] = __expf(acc[nf][1] - mn0);
            acc[nf][2] = __expf(acc[nf][2] - mn1);
            acc[nf][3] = __expf(acc[nf][3] - mn1);
            s0 += acc[nf][0] + acc[nf][1];
            s1 += acc[nf][2] + acc[nf][3];
        }
        #pragma unroll
        for (int o = 1; o <= 2; o <<= 1) {
            s0 += __shfl_xor_sync(0xffffffffu, s0, o);
            s1 += __shfl_xor_sync(0xffffffffu, s1, o);
        }
        l0v = l0v * sc0 + s0;
        l1v = l1v * sc1 + s1;
        #pragma unroll
        for (int nf = 0; nf < 8; nf++) {
            Oa[nf][0] *= sc0; Oa[nf][1] *= sc0;
            Oa[nf][2] *= sc1; Oa[nf][3] *= sc1;
        }

        #pragma unroll
        for (int nf = 0; nf < 8; nf++) {
            *(__half2*)&Ps[qrow*QST     + nf*8 + 2*c0] =
                __floats2half2_rn(acc[nf][0], acc[nf][1]);
            *(__half2*)&Ps[(qrow+8)*QST + nf*8 + 2*c0] =
                __floats2half2_rn(acc[nf][2], acc[nf][3]);
        }
        __syncwarp();
        #pragma unroll
        for (int kc = 0; kc < 4; kc++) {
            unsigned a4[4];
            ldsm4(a4[0], a4[1], a4[2], a4[3],
                  smaddr(&Ps[(w*16 + goff)*QST + kc*16 + khq]));
            #pragma unroll
            for (int dt = 0; dt < 4; dt++) {
                unsigned vb[4];
                ldsm4t(vb[0], vb[1], vb[2], vb[3],
                       smaddr(&Vs[(kc*16 + goff)*VST + dt*16 + khq]));
                mma16h(Oa[2*dt],   a4, vb[0], vb[1]);
                mma16h(Oa[2*dt+1], a4, vb[2], vb[3]);
            }
        }
        __syncwarp();
    }

    float inv0 = 1.0f / l0v, inv1 = 1.0f / l1v;
    int b = bh >> 4, h = bh & 15;
    __half* O0 = g_o1h + ((size_t)b*NN + q0 + qrow)*DMODEL + h*DK;
    __half* O1 = O0 + 8*DMODEL;
    #pragma unroll
    for (int nf = 0; nf < 8; nf++) {
        *(__half2*)(O0 + nf*8 + 2*c0) = __floats2half2_rn(Oa[nf][0]*inv0, Oa[nf][1]*inv0);
        *(__half2*)(O1 + nf*8 + 2*c0) = __floats2half2_rn(Oa[nf][2]*inv1, Oa[nf][3]*inv1);
    }
}

// ============================================================
extern "C" void kernel_launch(void* const* d_in, const int* in_sizes, int n_in,
                              void* d_out, int out_size) {
    const float* queries = (const float*)d_in[0];
    const float* keys    = (const float*)d_in[1];
    const float* values  = (const float*)d_in[2];
    const float* boxes   = (const float*)d_in[3];
    const float* Wq = (const float*)d_in[4];
    const float* bq = (const float*)d_in[5];
    const float* Wk = (const float*)d_in[6];
    const float* bk = (const float*)d_in[7];
    const float* Wv = (const float*)d_in[8];
    const float* bv = (const float*)d_in[9];
    const float* Wo = (const float*)d_in[10];
    const float* bo = (const float*)d_in[11];
    const float* Wg = (const float*)d_in[12];
    const float* bg = (const float*)d_in[13];
    float* out = (float*)d_out;

    cudaFuncSetAttribute(gemm_tc<0>, cudaFuncAttributeMaxDynamicSharedMemorySize, HSMEM);
    cudaFuncSetAttribute(gemm_tc<1>, cudaFuncAttributeMaxDynamicSharedMemorySize, HSMEM);
    cudaFuncSetAttribute(fused_attn, cudaFuncAttributeMaxDynamicSharedMemorySize,
                         FUSED_SMEM);

    // fork: side stream runs the geometry-bias chain (g_s), main stream runs
    // prep + QKV projections. Both join before fused_attn.
    cudaEventRecord(g_evFork, 0);
    cudaStreamWaitEvent(g_s2, g_evFork, 0);

    boxfeat_kernel<<<16, 256, 0, g_s2>>>(boxes);
    geom_kernel<<<dim3(32, 32, 8), 256, 0, g_s2>>>(Wg, bg);
    cudaEventRecord(g_evJoin, g_s2);

    prep_kernel<<<dim3(4096, 7), 256>>>(queries, keys, values, Wq, Wk, Wv, Wo);
    gemm_tc<0><<<dim3(8, 32, 3), 256, HSMEM>>>(bq, bk, bv, nullptr);

    cudaStreamWaitEvent(0, g_evJoin, 0);
    fused_attn<<<dim3(4, 128), 256, FUSED_SMEM>>>();
    gemm_tc<1><<<dim3(8, 32, 1), 256, HSMEM>>>(bo, nullptr, nullptr, out);
}